// round 1
// baseline (speedup 1.0000x reference)
#include <cuda_runtime.h>
#include <math.h>

#define Bn 16384
#define Dn 512
#define An 10
#define HIDN 256
#define MAIN_BLOCKS 1024

// ---------------- scratch (no allocations allowed) ----------------
__device__ float g_anch[An * Dn];          // anchors + pos_embedding
__device__ float g_an2[An];                // ||anch[a]||^2
__device__ float g_anchV[(An + 1) * Dn];   // anch @ Wv ; row 10 = qkv_b_v
__device__ float g_anchVW[(An + 1) * Dn];  // (anch @ Wv) @ proj_w ; row 10 = cbias
__device__ float g_weights[Bn];            // sigmoid gate per row
__device__ float g_partials[MAIN_BLOCKS];  // center-loss per-block partials

// ---------------- K0: anch = anchors + pos ; ||anch||^2 ----------------
__global__ void k0_setup(const float* __restrict__ anchors,
                         const float* __restrict__ pos) {
    int t = threadIdx.x;  // 512
    for (int i = t; i < An * Dn; i += 512) g_anch[i] = anchors[i] + pos[i];
    __syncthreads();
    int w = t >> 5, l = t & 31;
    if (w < An) {
        float s = 0.f;
        for (int k = l; k < Dn; k += 32) {
            float v = g_anch[w * Dn + k];
            s = fmaf(v, v, s);
        }
        #pragma unroll
        for (int o = 16; o; o >>= 1) s += __shfl_xor_sync(0xffffffffu, s, o);
        if (l == 0) g_an2[w] = s;
    }
}

// ---------------- K1: anchV = anch @ qkv_w[:, 2D:3D] ; row10 = qkv_b_v ----------------
__global__ void k1_anchV(const float* __restrict__ qkv_w,
                         const float* __restrict__ qkv_b) {
    int a = blockIdx.y;
    int j = blockIdx.x * 128 + threadIdx.x;
    if (a == An) {  // whole block takes this path (no divergent barrier)
        g_anchV[a * Dn + j] = qkv_b[2 * Dn + j];
        return;
    }
    __shared__ float row[Dn];
    for (int i = threadIdx.x; i < Dn; i += 128) row[i] = g_anch[a * Dn + i];
    __syncthreads();
    float acc = 0.f;
    #pragma unroll 4
    for (int k = 0; k < Dn; k++)
        acc = fmaf(row[k], __ldg(&qkv_w[k * (3 * Dn) + 2 * Dn + j]), acc);
    g_anchV[a * Dn + j] = acc;
}

// ---------------- K2: anchVW = anchV @ proj_w ; row10 += proj_b ----------------
__global__ void k2_anchVW(const float* __restrict__ proj_w,
                          const float* __restrict__ proj_b) {
    int a = blockIdx.y;
    int d = blockIdx.x * 128 + threadIdx.x;
    __shared__ float row[Dn];
    for (int i = threadIdx.x; i < Dn; i += 128) row[i] = g_anchV[a * Dn + i];
    __syncthreads();
    float acc = 0.f;
    #pragma unroll 4
    for (int j = 0; j < Dn; j++)
        acc = fmaf(row[j], __ldg(&proj_w[j * Dn + d]), acc);
    if (a == An) acc += proj_b[d];
    g_anchVW[a * Dn + d] = acc;
}

// ---------------- Kgemm: weights = sigmoid(relu(F@w1+b1)@w2+b2) ----------------
// M=16384, N=256, K=512. BM=64, BN=256, BK=32, 256 threads, 8x8 microtile.
__global__ __launch_bounds__(256, 2)
void kgemm_weights(const float* __restrict__ f,
                   const float* __restrict__ w1,
                   const float* __restrict__ b1,
                   const float* __restrict__ w2,
                   const float* __restrict__ b2) {
    __shared__ float As[64 * 33];   // [m][k], padded stride 33
    __shared__ float Bs[32 * 256];  // [k][n]
    const int tid = threadIdx.x;
    const int tm = tid & 7;         // 8 row-groups
    const int tn = tid >> 3;        // 32 col-groups
    const int m0 = blockIdx.x * 64;

    float acc[8][8];
    #pragma unroll
    for (int i = 0; i < 8; i++)
        #pragma unroll
        for (int j = 0; j < 8; j++) acc[i][j] = 0.f;

    for (int k0 = 0; k0 < Dn; k0 += 32) {
        // A tile: 64x32 = 512 float4, 2 per thread, scatter-store (pad 33)
        #pragma unroll
        for (int p = 0; p < 2; p++) {
            int idx = tid + p * 256;
            int row = idx >> 3, kq = idx & 7;
            float4 v = *(const float4*)&f[(size_t)(m0 + row) * Dn + k0 + kq * 4];
            float* dst = &As[row * 33 + kq * 4];
            dst[0] = v.x; dst[1] = v.y; dst[2] = v.z; dst[3] = v.w;
        }
        // B tile: 32x256 floats = 2048 float4, 8 per thread
        #pragma unroll
        for (int p = 0; p < 8; p++) {
            int idx = tid + p * 256;
            int kr = idx >> 6, nq = idx & 63;
            *(float4*)&Bs[kr * 256 + nq * 4] =
                *(const float4*)&w1[(size_t)(k0 + kr) * 256 + nq * 4];
        }
        __syncthreads();
        #pragma unroll
        for (int k = 0; k < 32; k++) {
            float a[8], b[8];
            #pragma unroll
            for (int i = 0; i < 8; i++) a[i] = As[(tm * 8 + i) * 33 + k];
            float4 t0 = *(float4*)&Bs[k * 256 + tn * 8];
            float4 t1 = *(float4*)&Bs[k * 256 + tn * 8 + 4];
            b[0] = t0.x; b[1] = t0.y; b[2] = t0.z; b[3] = t0.w;
            b[4] = t1.x; b[5] = t1.y; b[6] = t1.z; b[7] = t1.w;
            #pragma unroll
            for (int i = 0; i < 8; i++)
                #pragma unroll
                for (int j = 0; j < 8; j++)
                    acc[i][j] = fmaf(a[i], b[j], acc[i][j]);
        }
        __syncthreads();
    }

    // epilogue: relu(+b1), dot w2 over owned 8 cols, reduce across 32 col-groups
    float p[8];
    #pragma unroll
    for (int i = 0; i < 8; i++) {
        float s = 0.f;
        #pragma unroll
        for (int j = 0; j < 8; j++) {
            int col = tn * 8 + j;
            float h = fmaxf(acc[i][j] + __ldg(&b1[col]), 0.f);
            s = fmaf(h, __ldg(&w2[col]), s);
        }
        p[i] = s;
    }
    __syncthreads();
    float* red = As;  // 64x32 fits in As
    #pragma unroll
    for (int i = 0; i < 8; i++) red[(tm * 8 + i) * 32 + tn] = p[i];
    __syncthreads();
    if (tid < 64) {
        float s = 0.f;
        #pragma unroll
        for (int c = 0; c < 32; c++) s += red[tid * 32 + c];
        s += b2[0];
        g_weights[m0 + tid] = 1.f / (1.f + expf(-s));
    }
}

// ---------------- Kmain: distances, softmax, refined, attention, center partials ----------------
// 512 threads = 16 warps, 1 warp per row, 16 rows/block, grid 1024.
__global__ __launch_bounds__(512)
void kmain(const float* __restrict__ feat,
           float* __restrict__ out_refined,
           float* __restrict__ out_att) {
    __shared__ float sA[An * Dn];         // 20KB anch
    __shared__ float sW[(An + 1) * Dn];   // 22KB anchVW (+cbias row)
    __shared__ float sn2[An];
    __shared__ float red[16];
    const int tid = threadIdx.x;
    for (int i = tid; i < An * Dn; i += 512) sA[i] = g_anch[i];
    for (int i = tid; i < (An + 1) * Dn; i += 512) sW[i] = g_anchVW[i];
    if (tid < An) sn2[tid] = g_an2[tid];
    __syncthreads();

    const int wid = tid >> 5, l = tid & 31;
    const int r = blockIdx.x * 16 + wid;
    const float* f = feat + (size_t)r * Dn;

    float4 fv[4];
    #pragma unroll
    for (int j = 0; j < 4; j++) fv[j] = *(const float4*)&f[j * 128 + l * 4];

    // 11 warp reductions: dots with 10 anchors + ||f||^2
    float v11[11];
    {
        float s = 0.f;
        #pragma unroll
        for (int j = 0; j < 4; j++) {
            s = fmaf(fv[j].x, fv[j].x, s); s = fmaf(fv[j].y, fv[j].y, s);
            s = fmaf(fv[j].z, fv[j].z, s); s = fmaf(fv[j].w, fv[j].w, s);
        }
        v11[10] = s;
    }
    #pragma unroll
    for (int a = 0; a < An; a++) {
        float d = 0.f;
        #pragma unroll
        for (int j = 0; j < 4; j++) {
            float4 av = *(const float4*)&sA[a * Dn + j * 128 + l * 4];
            d = fmaf(fv[j].x, av.x, d); d = fmaf(fv[j].y, av.y, d);
            d = fmaf(fv[j].z, av.z, d); d = fmaf(fv[j].w, av.w, d);
        }
        v11[a] = d;
    }
    #pragma unroll
    for (int a = 0; a < 11; a++) {
        #pragma unroll
        for (int o = 16; o; o >>= 1) v11[a] += __shfl_xor_sync(0xffffffffu, v11[a], o);
    }

    const float fn2 = v11[10];
    const float inv_temp = rsqrtf(fn2);   // 1/||f||
    float att[An];
    float mx = -1e30f;
    #pragma unroll
    for (int a = 0; a < An; a++) {
        float d2 = fn2 - 2.f * v11[a] + sn2[a];
        float dist = sqrtf(fmaxf(d2, 0.f));
        float lg = -dist * inv_temp;
        att[a] = lg;
        mx = fmaxf(mx, lg);
    }
    float se = 0.f;
    #pragma unroll
    for (int a = 0; a < An; a++) { att[a] = __expf(att[a] - mx); se += att[a]; }
    const float inv_se = 1.f / se;
    #pragma unroll
    for (int a = 0; a < An; a++) att[a] *= inv_se;

    const float w = g_weights[r];

    float cp = 0.f;
    #pragma unroll
    for (int j = 0; j < 4; j++) {
        int base = j * 128 + l * 4;
        float4 cb = *(const float4*)&sW[An * Dn + base];
        float4 ac = make_float4(0.f, 0.f, 0.f, 0.f);
        #pragma unroll
        for (int a = 0; a < An; a++) {
            float4 av = *(const float4*)&sW[a * Dn + base];
            ac.x = fmaf(att[a], av.x, ac.x); ac.y = fmaf(att[a], av.y, ac.y);
            ac.z = fmaf(att[a], av.z, ac.z); ac.w = fmaf(att[a], av.w, ac.w);
        }
        float4 rr;
        rr.x = fmaf(w, ac.x, cb.x); rr.y = fmaf(w, ac.y, cb.y);
        rr.z = fmaf(w, ac.z, cb.z); rr.w = fmaf(w, ac.w, cb.w);
        *(float4*)&out_refined[(size_t)r * Dn + base] = rr;
        float dx = fv[j].x - rr.x; cp = fmaf(dx, dx, cp);
        dx = fv[j].y - rr.y; cp = fmaf(dx, dx, cp);
        dx = fv[j].z - rr.z; cp = fmaf(dx, dx, cp);
        dx = fv[j].w - rr.w; cp = fmaf(dx, dx, cp);
    }

    #pragma unroll
    for (int a = 0; a < An; a++)
        if (l == a) out_att[(size_t)r * An + a] = att[a];

    #pragma unroll
    for (int o = 16; o; o >>= 1) cp += __shfl_xor_sync(0xffffffffu, cp, o);
    if (l == 0) red[wid] = cp;
    __syncthreads();
    if (tid == 0) {
        float t = 0.f;
        #pragma unroll
        for (int i = 0; i < 16; i++) t += red[i];
        g_partials[blockIdx.x] = t;
    }
}

// ---------------- Kfinal: total_loss (deterministic reductions) ----------------
__global__ void kfinal(const float* __restrict__ anchors,
                       const float* __restrict__ clw,
                       float* __restrict__ out_scalar) {
    __shared__ float sm[256];
    int t = threadIdx.x;
    float s = 0.f;
    for (int i = t; i < MAIN_BLOCKS; i += 256) s += g_partials[i];
    sm[t] = s;
    __syncthreads();
    for (int o = 128; o; o >>= 1) {
        if (t < o) sm[t] += sm[t + o];
        __syncthreads();
    }
    float center = sm[0] * (1.f / (float)Bn);
    __syncthreads();

    // diversity: 45 upper-triangle pairs of ORIGINAL anchors
    float pd = 0.f;
    if (t < 45) {
        int i = 0, p = t;
        while (p >= 9 - i) { p -= 9 - i; i++; }
        int j = i + 1 + p;
        float ss = 0.f;
        for (int d = 0; d < Dn; d++) {
            float df = anchors[i * Dn + d] - anchors[j * Dn + d];
            ss = fmaf(df, df, ss);
        }
        pd = sqrtf(fmaxf(ss, 0.f));
    }
    sm[t] = pd;
    __syncthreads();
    for (int o = 128; o; o >>= 1) {
        if (t < o) sm[t] += sm[t + o];
        __syncthreads();
    }
    if (t == 0) {
        float div = -(sm[0] / 45.f);
        out_scalar[0] = clw[0] * center + 0.1f * div;
    }
}

// ---------------- launch ----------------
extern "C" void kernel_launch(void* const* d_in, const int* in_sizes, int n_in,
                              void* d_out, int out_size) {
    const float* features = (const float*)d_in[0];
    const float* anchors  = (const float*)d_in[1];
    const float* pos      = (const float*)d_in[2];
    const float* qkv_w    = (const float*)d_in[3];
    const float* qkv_b    = (const float*)d_in[4];
    const float* proj_w   = (const float*)d_in[5];
    const float* proj_b   = (const float*)d_in[6];
    const float* w1       = (const float*)d_in[7];
    const float* b1       = (const float*)d_in[8];
    const float* w2       = (const float*)d_in[9];
    const float* b2       = (const float*)d_in[10];
    const float* clw      = (const float*)d_in[11];

    float* out         = (float*)d_out;
    float* out_refined = out;                        // B*D
    float* out_scalar  = out + (size_t)Bn * Dn;      // 1
    float* out_att     = out + (size_t)Bn * Dn + 1;  // B*A

    kgemm_weights<<<Bn / 64, 256>>>(features, w1, b1, w2, b2);
    k0_setup<<<1, 512>>>(anchors, pos);
    k1_anchV<<<dim3(4, An + 1), 128>>>(qkv_w, qkv_b);
    k2_anchVW<<<dim3(4, An + 1), 128>>>(proj_w, proj_b);
    kmain<<<MAIN_BLOCKS, 512>>>(features, out_refined, out_att);
    kfinal<<<1, 256>>>(anchors, clw, out_scalar);
}

// round 4
// speedup vs baseline: 1.2075x; 1.2075x over previous
#include <cuda_runtime.h>
#include <math.h>
#include <stdint.h>

#define Bn 16384
#define Dn 512
#define An 10
#define MAIN_BLOCKS 1024

// ---------------- scratch (no allocations allowed) ----------------
__device__ float g_anch[An * Dn];          // anchors + pos_embedding
__device__ float g_an2[An];                // ||anch[a]||^2
__device__ float g_anchV[(An + 1) * Dn];   // anch @ Wv ; row 10 = qkv_b_v
__device__ float g_anchVW[(An + 1) * Dn];  // (anch @ Wv) @ proj_w ; row 10 = cbias
__device__ float g_weights[Bn];            // sigmoid gate per row
__device__ float g_partials[MAIN_BLOCKS];  // center-loss per-block partials

// ---------------- K0: anch = anchors + pos ; ||anch||^2 ----------------
__global__ void k0_setup(const float* __restrict__ anchors,
                         const float* __restrict__ pos) {
    int t = threadIdx.x;  // 512
    for (int i = t; i < An * Dn; i += 512) g_anch[i] = anchors[i] + pos[i];
    __syncthreads();
    int w = t >> 5, l = t & 31;
    if (w < An) {
        float s = 0.f;
        for (int k = l; k < Dn; k += 32) {
            float v = g_anch[w * Dn + k];
            s = fmaf(v, v, s);
        }
        #pragma unroll
        for (int o = 16; o; o >>= 1) s += __shfl_xor_sync(0xffffffffu, s, o);
        if (l == 0) g_an2[w] = s;
    }
}

// ---------------- K1: anchV = anch @ qkv_w[:, 2D:3D] ; row10 = qkv_b_v ----
// Warp-per-output-column: lanes split K (16 independent loads, MLP 16).
__global__ void k1_anchV(const float* __restrict__ qkv_w,
                         const float* __restrict__ qkv_b) {
    int a = blockIdx.y;
    int w = threadIdx.x >> 5, l = threadIdx.x & 31;
    int j = blockIdx.x * 8 + w;
    if (a == An) {
        if (l == 0) g_anchV[An * Dn + j] = qkv_b[2 * Dn + j];
        return;
    }
    float s = 0.f;
    #pragma unroll
    for (int kk = 0; kk < 16; kk++) {
        int k = kk * 32 + l;
        s = fmaf(g_anch[a * Dn + k],
                 __ldg(&qkv_w[(size_t)k * (3 * Dn) + 2 * Dn + j]), s);
    }
    #pragma unroll
    for (int o = 16; o; o >>= 1) s += __shfl_xor_sync(0xffffffffu, s, o);
    if (l == 0) g_anchV[a * Dn + j] = s;
}

// ---------------- K2: anchVW = anchV @ proj_w ; row10 += proj_b ----------
__global__ void k2_anchVW(const float* __restrict__ proj_w,
                          const float* __restrict__ proj_b) {
    int a = blockIdx.y;
    int w = threadIdx.x >> 5, l = threadIdx.x & 31;
    int d = blockIdx.x * 8 + w;
    float s = 0.f;
    #pragma unroll
    for (int kk = 0; kk < 16; kk++) {
        int j = kk * 32 + l;
        s = fmaf(g_anchV[a * Dn + j], __ldg(&proj_w[(size_t)j * Dn + d]), s);
    }
    #pragma unroll
    for (int o = 16; o; o >>= 1) s += __shfl_xor_sync(0xffffffffu, s, o);
    if (l == 0) {
        if (a == An) s += proj_b[d];
        g_anchVW[a * Dn + d] = s;
    }
}

// ---------------- Kgemm: weights = sigmoid(relu(F@w1+b1)@w2+b2) ----------
// tf32 mma.sync m16n8k8. M=16384, N=256 (full), K=512.
// BM=128, BN=256, BK=16. 512 threads = 16 warps (4x4), warp tile 32x64.
// Static smem: As 128*20*4=10.0KB + Bs 16*264*4=16.5KB = 26.5KB (<48KB cap).
#define BM 128
#define BK 16
#define AST 20    // As row stride (floats): rows*20 mod 32 all distinct
#define BST 264   // Bs row stride (floats): tg*8+g covers banks 0..31

__device__ __forceinline__ uint32_t f2tf32(float x) {
    uint32_t u;
    asm("cvt.rna.tf32.f32 %0, %1;" : "=r"(u) : "f"(x));
    return u;
}

__device__ __forceinline__ void mma_tf32(float c[4], const uint32_t a[4],
                                         const uint32_t b[2]) {
    asm volatile(
        "mma.sync.aligned.m16n8k8.row.col.f32.tf32.tf32.f32 "
        "{%0,%1,%2,%3}, {%4,%5,%6,%7}, {%8,%9}, {%0,%1,%2,%3};"
        : "+f"(c[0]), "+f"(c[1]), "+f"(c[2]), "+f"(c[3])
        : "r"(a[0]), "r"(a[1]), "r"(a[2]), "r"(a[3]), "r"(b[0]), "r"(b[1]));
}

__global__ __launch_bounds__(512, 2)
void kgemm_weights(const float* __restrict__ f,
                   const float* __restrict__ w1,
                   const float* __restrict__ b1,
                   const float* __restrict__ w2,
                   const float* __restrict__ b2) {
    __shared__ float As[BM * AST];   // 10.0 KB
    __shared__ float Bs[BK * BST];   // 16.5 KB
    const int tid = threadIdx.x;
    const int wid = tid >> 5, l = tid & 31;
    const int wr = wid & 3;          // warp row group: rows wr*32..+32
    const int wc = wid >> 2;         // warp col group: cols wc*64..+64
    const int g = l >> 2, tg = l & 3;
    const int m0 = blockIdx.x * BM;

    float C[2][8][4];
    #pragma unroll
    for (int mt = 0; mt < 2; mt++)
        #pragma unroll
        for (int nt = 0; nt < 8; nt++)
            #pragma unroll
            for (int i = 0; i < 4; i++) C[mt][nt][i] = 0.f;

    for (int k0 = 0; k0 < Dn; k0 += BK) {
        // A tile 128x16 = 512 float4, 1 per thread
        {
            int row = tid >> 2, c4 = tid & 3;
            float4 v = *(const float4*)&f[(size_t)(m0 + row) * Dn + k0 + c4 * 4];
            float4 o;
            o.x = __uint_as_float(f2tf32(v.x));
            o.y = __uint_as_float(f2tf32(v.y));
            o.z = __uint_as_float(f2tf32(v.z));
            o.w = __uint_as_float(f2tf32(v.w));
            *(float4*)&As[row * AST + c4 * 4] = o;
        }
        // B tile 16x256 = 1024 float4, 2 per thread
        #pragma unroll
        for (int p = 0; p < 2; p++) {
            int idx = tid + p * 512;
            int kr = idx >> 6, n4 = idx & 63;
            float4 v = *(const float4*)&w1[(size_t)(k0 + kr) * 256 + n4 * 4];
            float4 o;
            o.x = __uint_as_float(f2tf32(v.x));
            o.y = __uint_as_float(f2tf32(v.y));
            o.z = __uint_as_float(f2tf32(v.z));
            o.w = __uint_as_float(f2tf32(v.w));
            *(float4*)&Bs[kr * BST + n4 * 4] = o;
        }
        __syncthreads();
        #pragma unroll
        for (int ks = 0; ks < 2; ks++) {
            uint32_t a[2][4];
            const int ar = wr * 32 + g;
            const int ac = ks * 8 + tg;
            #pragma unroll
            for (int mt = 0; mt < 2; mt++) {
                a[mt][0] = __float_as_uint(As[(ar + mt * 16) * AST + ac]);
                a[mt][1] = __float_as_uint(As[(ar + mt * 16 + 8) * AST + ac]);
                a[mt][2] = __float_as_uint(As[(ar + mt * 16) * AST + ac + 4]);
                a[mt][3] = __float_as_uint(As[(ar + mt * 16 + 8) * AST + ac + 4]);
            }
            #pragma unroll
            for (int nt = 0; nt < 8; nt++) {
                uint32_t b[2];
                const int bn = wc * 64 + nt * 8 + g;
                const int bk = ks * 8 + tg;
                b[0] = __float_as_uint(Bs[bk * BST + bn]);
                b[1] = __float_as_uint(Bs[(bk + 4) * BST + bn]);
                mma_tf32(C[0][nt], a[0], b);
                mma_tf32(C[1][nt], a[1], b);
            }
        }
        __syncthreads();
    }

    // epilogue: relu(+b1), dot w2 per thread over owned cols
    float bb1[8][2], ww2[8][2];
    #pragma unroll
    for (int nt = 0; nt < 8; nt++) {
        int n0 = wc * 64 + nt * 8 + tg * 2;
        bb1[nt][0] = __ldg(&b1[n0]);     bb1[nt][1] = __ldg(&b1[n0 + 1]);
        ww2[nt][0] = __ldg(&w2[n0]);     ww2[nt][1] = __ldg(&w2[n0 + 1]);
    }
    float part[2][2];
    part[0][0] = part[0][1] = part[1][0] = part[1][1] = 0.f;
    #pragma unroll
    for (int mt = 0; mt < 2; mt++)
        #pragma unroll
        for (int nt = 0; nt < 8; nt++) {
            part[mt][0] = fmaf(fmaxf(C[mt][nt][0] + bb1[nt][0], 0.f), ww2[nt][0], part[mt][0]);
            part[mt][0] = fmaf(fmaxf(C[mt][nt][1] + bb1[nt][1], 0.f), ww2[nt][1], part[mt][0]);
            part[mt][1] = fmaf(fmaxf(C[mt][nt][2] + bb1[nt][0], 0.f), ww2[nt][0], part[mt][1]);
            part[mt][1] = fmaf(fmaxf(C[mt][nt][3] + bb1[nt][1], 0.f), ww2[nt][1], part[mt][1]);
        }
    __syncthreads();
    float* red = As;  // reuse: 128 rows x 16 slots = 8KB <= As
    #pragma unroll
    for (int mt = 0; mt < 2; mt++) {
        int r0 = wr * 32 + mt * 16 + g;
        red[r0 * 16 + wc * 4 + tg]       = part[mt][0];
        red[(r0 + 8) * 16 + wc * 4 + tg] = part[mt][1];
    }
    __syncthreads();
    if (tid < BM) {
        float s = 0.f;
        #pragma unroll
        for (int i = 0; i < 16; i++) s += red[tid * 16 + i];
        s += __ldg(&b2[0]);
        g_weights[m0 + tid] = 1.f / (1.f + expf(-s));
    }
}

// ---------------- Kmain: distances, softmax, refined, attention, center ---
__global__ __launch_bounds__(512)
void kmain(const float* __restrict__ feat,
           float* __restrict__ out_refined,
           float* __restrict__ out_att) {
    __shared__ float sA[An * Dn];
    __shared__ float sW[(An + 1) * Dn];
    __shared__ float sn2[An];
    __shared__ float red[16];
    const int tid = threadIdx.x;
    for (int i = tid; i < An * Dn; i += 512) sA[i] = g_anch[i];
    for (int i = tid; i < (An + 1) * Dn; i += 512) sW[i] = g_anchVW[i];
    if (tid < An) sn2[tid] = g_an2[tid];
    __syncthreads();

    const int wid = tid >> 5, l = tid & 31;
    const int r = blockIdx.x * 16 + wid;
    const float* f = feat + (size_t)r * Dn;

    float4 fv[4];
    #pragma unroll
    for (int j = 0; j < 4; j++) fv[j] = *(const float4*)&f[j * 128 + l * 4];

    float v11[11];
    {
        float s = 0.f;
        #pragma unroll
        for (int j = 0; j < 4; j++) {
            s = fmaf(fv[j].x, fv[j].x, s); s = fmaf(fv[j].y, fv[j].y, s);
            s = fmaf(fv[j].z, fv[j].z, s); s = fmaf(fv[j].w, fv[j].w, s);
        }
        v11[10] = s;
    }
    #pragma unroll
    for (int a = 0; a < An; a++) {
        float d = 0.f;
        #pragma unroll
        for (int j = 0; j < 4; j++) {
            float4 av = *(const float4*)&sA[a * Dn + j * 128 + l * 4];
            d = fmaf(fv[j].x, av.x, d); d = fmaf(fv[j].y, av.y, d);
            d = fmaf(fv[j].z, av.z, d); d = fmaf(fv[j].w, av.w, d);
        }
        v11[a] = d;
    }
    #pragma unroll
    for (int a = 0; a < 11; a++) {
        #pragma unroll
        for (int o = 16; o; o >>= 1) v11[a] += __shfl_xor_sync(0xffffffffu, v11[a], o);
    }

    const float fn2 = v11[10];
    const float inv_temp = rsqrtf(fn2);
    float att[An];
    float mx = -1e30f;
    #pragma unroll
    for (int a = 0; a < An; a++) {
        float d2 = fn2 - 2.f * v11[a] + sn2[a];
        float dist = sqrtf(fmaxf(d2, 0.f));
        float lg = -dist * inv_temp;
        att[a] = lg;
        mx = fmaxf(mx, lg);
    }
    float se = 0.f;
    #pragma unroll
    for (int a = 0; a < An; a++) { att[a] = __expf(att[a] - mx); se += att[a]; }
    const float inv_se = 1.f / se;
    #pragma unroll
    for (int a = 0; a < An; a++) att[a] *= inv_se;

    const float w = g_weights[r];

    float cp = 0.f;
    #pragma unroll
    for (int j = 0; j < 4; j++) {
        int base = j * 128 + l * 4;
        float4 cb = *(const float4*)&sW[An * Dn + base];
        float4 ac = make_float4(0.f, 0.f, 0.f, 0.f);
        #pragma unroll
        for (int a = 0; a < An; a++) {
            float4 av = *(const float4*)&sW[a * Dn + base];
            ac.x = fmaf(att[a], av.x, ac.x); ac.y = fmaf(att[a], av.y, ac.y);
            ac.z = fmaf(att[a], av.z, ac.z); ac.w = fmaf(att[a], av.w, ac.w);
        }
        float4 rr;
        rr.x = fmaf(w, ac.x, cb.x); rr.y = fmaf(w, ac.y, cb.y);
        rr.z = fmaf(w, ac.z, cb.z); rr.w = fmaf(w, ac.w, cb.w);
        *(float4*)&out_refined[(size_t)r * Dn + base] = rr;
        float dx = fv[j].x - rr.x; cp = fmaf(dx, dx, cp);
        dx = fv[j].y - rr.y; cp = fmaf(dx, dx, cp);
        dx = fv[j].z - rr.z; cp = fmaf(dx, dx, cp);
        dx = fv[j].w - rr.w; cp = fmaf(dx, dx, cp);
    }

    #pragma unroll
    for (int a = 0; a < An; a++)
        if (l == a) out_att[(size_t)r * An + a] = att[a];

    #pragma unroll
    for (int o = 16; o; o >>= 1) cp += __shfl_xor_sync(0xffffffffu, cp, o);
    if (l == 0) red[wid] = cp;
    __syncthreads();
    if (tid == 0) {
        float t = 0.f;
        #pragma unroll
        for (int i = 0; i < 16; i++) t += red[i];
        g_partials[blockIdx.x] = t;
    }
}

// ---------------- Kfinal: total_loss (parallel, deterministic) -----------
__global__ void kfinal(const float* __restrict__ anchors,
                       const float* __restrict__ clw,
                       float* __restrict__ out_scalar) {
    __shared__ float sm[32];
    const int tid = threadIdx.x;  // 512
    const int w = tid >> 5, l = tid & 31;

    float s = g_partials[tid] + g_partials[tid + 512];
    #pragma unroll
    for (int o = 16; o; o >>= 1) s += __shfl_xor_sync(0xffffffffu, s, o);
    if (l == 0) sm[w] = s;

    float pd = 0.f;
    #pragma unroll
    for (int pp = 0; pp < 3; pp++) {
        int p = w + pp * 16;
        if (p < 45) {  // warp-uniform
            int i = 0, q = p;
            while (q >= 9 - i) { q -= 9 - i; i++; }
            int j = i + 1 + q;
            float ss = 0.f;
            #pragma unroll
            for (int dd = 0; dd < 16; dd++) {
                float df = anchors[i * Dn + dd * 32 + l] -
                           anchors[j * Dn + dd * 32 + l];
                ss = fmaf(df, df, ss);
            }
            #pragma unroll
            for (int o = 16; o; o >>= 1) ss += __shfl_xor_sync(0xffffffffu, ss, o);
            pd += sqrtf(fmaxf(ss, 0.f));
        }
    }
    if (l == 0) sm[16 + w] = pd;
    __syncthreads();
    if (tid == 0) {
        float c = 0.f, d = 0.f;
        #pragma unroll
        for (int i = 0; i < 16; i++) { c += sm[i]; d += sm[16 + i]; }
        float center = c * (1.f / (float)Bn);
        float div = -(d / 45.f);
        out_scalar[0] = clw[0] * center + 0.1f * div;
    }
}

// ---------------- launch ----------------
extern "C" void kernel_launch(void* const* d_in, const int* in_sizes, int n_in,
                              void* d_out, int out_size) {
    const float* features = (const float*)d_in[0];
    const float* anchors  = (const float*)d_in[1];
    const float* pos      = (const float*)d_in[2];
    const float* qkv_w    = (const float*)d_in[3];
    const float* qkv_b    = (const float*)d_in[4];
    const float* proj_w   = (const float*)d_in[5];
    const float* proj_b   = (const float*)d_in[6];
    const float* w1       = (const float*)d_in[7];
    const float* b1       = (const float*)d_in[8];
    const float* w2       = (const float*)d_in[9];
    const float* b2       = (const float*)d_in[10];
    const float* clw      = (const float*)d_in[11];

    float* out         = (float*)d_out;
    float* out_refined = out;                        // B*D
    float* out_scalar  = out + (size_t)Bn * Dn;      // 1
    float* out_att     = out + (size_t)Bn * Dn + 1;  // B*A

    kgemm_weights<<<Bn / BM, 512>>>(features, w1, b1, w2, b2);
    k0_setup<<<1, 512>>>(anchors, pos);
    k1_anchV<<<dim3(Dn / 8, An + 1), 256>>>(qkv_w, qkv_b);
    k2_anchVW<<<dim3(Dn / 8, An + 1), 256>>>(proj_w, proj_b);
    kmain<<<MAIN_BLOCKS, 512>>>(features, out_refined, out_att);
    kfinal<<<1, 512>>>(anchors, clw, out_scalar);
}

// round 5
// speedup vs baseline: 1.2974x; 1.0744x over previous
#include <cuda_runtime.h>
#include <math.h>
#include <stdint.h>

#define Bn 16384
#define Dn 512
#define An 10
#define KMAIN_BLOCKS 256
#define KSPLIT 8          // k-chunks for k1/k2 partials
#define KCH (Dn / KSPLIT) // 64

// ---------------- scratch (no allocations allowed) ----------------
__device__ float g_anch[An * Dn];            // anchors + pos_embedding
__device__ float g_an2[An];                  // ||anch[a]||^2
__device__ float g_anchV[(An + 1) * Dn];     // anch @ Wv ; row 10 = qkv_b_v
__device__ float g_anchVW[(An + 1) * Dn];    // (anch @ Wv) @ proj_w ; row10 = cbias
__device__ float g_part[KSPLIT * (An + 1) * Dn];  // matvec k-split partials (reused)
__device__ float g_weights[Bn];              // sigmoid gate per row
__device__ float g_partials[KMAIN_BLOCKS];   // center-loss per-block partials

// ---------------- K0: anch = anchors + pos ; ||anch||^2 ----------------
__global__ void k0_setup(const float* __restrict__ anchors,
                         const float* __restrict__ pos) {
    int t = threadIdx.x;  // 512
    for (int i = t; i < An * Dn; i += 512) g_anch[i] = anchors[i] + pos[i];
    __syncthreads();
    int w = t >> 5, l = t & 31;
    if (w < An) {
        float s = 0.f;
        for (int k = l; k < Dn; k += 32) {
            float v = g_anch[w * Dn + k];
            s = fmaf(v, v, s);
        }
        #pragma unroll
        for (int o = 16; o; o >>= 1) s += __shfl_xor_sync(0xffffffffu, s, o);
        if (l == 0) g_an2[w] = s;
    }
}

// ---------------- K1 part: partial anchV over a k-chunk (coalesced) ------
// grid (2, KSPLIT), block 256. Thread owns column j; loads qkv_w coalesced.
__global__ void k1_part(const float* __restrict__ qkv_w) {
    __shared__ float sa[An * KCH];
    const int tid = threadIdx.x;
    const int kc = blockIdx.y, k0 = kc * KCH;
    const int j = blockIdx.x * 256 + tid;
    for (int i = tid; i < An * KCH; i += 256) {
        int a = i / KCH, k = i % KCH;
        sa[i] = g_anch[a * Dn + k0 + k];
    }
    __syncthreads();
    float acc[An];
    #pragma unroll
    for (int a = 0; a < An; a++) acc[a] = 0.f;
    #pragma unroll 8
    for (int k = 0; k < KCH; k++) {
        float w = __ldg(&qkv_w[(size_t)(k0 + k) * (3 * Dn) + 2 * Dn + j]);
        #pragma unroll
        for (int a = 0; a < An; a++) acc[a] = fmaf(sa[a * KCH + k], w, acc[a]);
    }
    #pragma unroll
    for (int a = 0; a < An; a++)
        g_part[kc * ((An + 1) * Dn) + a * Dn + j] = acc[a];
}

// ---------------- K1 reduce: sum partials ; row10 = qkv_b_v --------------
// grid (An+1), block 512.
__global__ void k1_reduce(const float* __restrict__ qkv_b) {
    const int a = blockIdx.x;
    const int j = threadIdx.x;
    if (a == An) {
        g_anchV[An * Dn + j] = qkv_b[2 * Dn + j];
        return;
    }
    float s = 0.f;
    #pragma unroll
    for (int kc = 0; kc < KSPLIT; kc++)
        s += g_part[kc * ((An + 1) * Dn) + a * Dn + j];
    g_anchV[a * Dn + j] = s;
}

// ---------------- K2 part: partial anchVW over a k-chunk (coalesced) -----
// grid (2, KSPLIT), block 256. 11 accumulators (bias row included).
__global__ void k2_part(const float* __restrict__ proj_w) {
    __shared__ float sa[(An + 1) * KCH];
    const int tid = threadIdx.x;
    const int kc = blockIdx.y, k0 = kc * KCH;
    const int d = blockIdx.x * 256 + tid;
    for (int i = tid; i < (An + 1) * KCH; i += 256) {
        int a = i / KCH, k = i % KCH;
        sa[i] = g_anchV[a * Dn + k0 + k];
    }
    __syncthreads();
    float acc[An + 1];
    #pragma unroll
    for (int a = 0; a <= An; a++) acc[a] = 0.f;
    #pragma unroll 8
    for (int k = 0; k < KCH; k++) {
        float w = __ldg(&proj_w[(size_t)(k0 + k) * Dn + d]);
        #pragma unroll
        for (int a = 0; a <= An; a++) acc[a] = fmaf(sa[a * KCH + k], w, acc[a]);
    }
    #pragma unroll
    for (int a = 0; a <= An; a++)
        g_part[kc * ((An + 1) * Dn) + a * Dn + d] = acc[a];
}

// ---------------- K2 reduce: sum partials ; row10 += proj_b --------------
__global__ void k2_reduce(const float* __restrict__ proj_b) {
    const int a = blockIdx.x;
    const int d = threadIdx.x;
    float s = 0.f;
    #pragma unroll
    for (int kc = 0; kc < KSPLIT; kc++)
        s += g_part[kc * ((An + 1) * Dn) + a * Dn + d];
    if (a == An) s += proj_b[d];
    g_anchVW[a * Dn + d] = s;
}

// ---------------- Kgemm: weights = sigmoid(relu(F@w1+b1)@w2+b2) ----------
// tf32 mma.sync m16n8k8. M=16384, N=256 (full), K=512.
// BM=128, BN=256, BK=16. 512 threads = 16 warps (4x4), warp tile 32x64.
#define BM 128
#define BK 16
#define AST 20    // As row stride (floats): rows*20 mod 32 all distinct
#define BST 264   // Bs row stride (floats): tg*8+g covers banks 0..31

__device__ __forceinline__ uint32_t f2tf32(float x) {
    uint32_t u;
    asm("cvt.rna.tf32.f32 %0, %1;" : "=r"(u) : "f"(x));
    return u;
}

__device__ __forceinline__ void mma_tf32(float c[4], const uint32_t a[4],
                                         const uint32_t b[2]) {
    asm volatile(
        "mma.sync.aligned.m16n8k8.row.col.f32.tf32.tf32.f32 "
        "{%0,%1,%2,%3}, {%4,%5,%6,%7}, {%8,%9}, {%0,%1,%2,%3};"
        : "+f"(c[0]), "+f"(c[1]), "+f"(c[2]), "+f"(c[3])
        : "r"(a[0]), "r"(a[1]), "r"(a[2]), "r"(a[3]), "r"(b[0]), "r"(b[1]));
}

__global__ __launch_bounds__(512)
void kgemm_weights(const float* __restrict__ f,
                   const float* __restrict__ w1,
                   const float* __restrict__ b1,
                   const float* __restrict__ w2,
                   const float* __restrict__ b2) {
    __shared__ float As[BM * AST];   // 10.0 KB
    __shared__ float Bs[BK * BST];   // 16.5 KB
    const int tid = threadIdx.x;
    const int wid = tid >> 5, l = tid & 31;
    const int wr = wid & 3;
    const int wc = wid >> 2;
    const int g = l >> 2, tg = l & 3;
    const int m0 = blockIdx.x * BM;

    float C[2][8][4];
    #pragma unroll
    for (int mt = 0; mt < 2; mt++)
        #pragma unroll
        for (int nt = 0; nt < 8; nt++)
            #pragma unroll
            for (int i = 0; i < 4; i++) C[mt][nt][i] = 0.f;

    for (int k0 = 0; k0 < Dn; k0 += BK) {
        {
            int row = tid >> 2, c4 = tid & 3;
            float4 v = *(const float4*)&f[(size_t)(m0 + row) * Dn + k0 + c4 * 4];
            float4 o;
            o.x = __uint_as_float(f2tf32(v.x));
            o.y = __uint_as_float(f2tf32(v.y));
            o.z = __uint_as_float(f2tf32(v.z));
            o.w = __uint_as_float(f2tf32(v.w));
            *(float4*)&As[row * AST + c4 * 4] = o;
        }
        #pragma unroll
        for (int p = 0; p < 2; p++) {
            int idx = tid + p * 512;
            int kr = idx >> 6, n4 = idx & 63;
            float4 v = *(const float4*)&w1[(size_t)(k0 + kr) * 256 + n4 * 4];
            float4 o;
            o.x = __uint_as_float(f2tf32(v.x));
            o.y = __uint_as_float(f2tf32(v.y));
            o.z = __uint_as_float(f2tf32(v.z));
            o.w = __uint_as_float(f2tf32(v.w));
            *(float4*)&Bs[kr * BST + n4 * 4] = o;
        }
        __syncthreads();
        #pragma unroll
        for (int ks = 0; ks < 2; ks++) {
            uint32_t a[2][4];
            const int ar = wr * 32 + g;
            const int ac = ks * 8 + tg;
            #pragma unroll
            for (int mt = 0; mt < 2; mt++) {
                a[mt][0] = __float_as_uint(As[(ar + mt * 16) * AST + ac]);
                a[mt][1] = __float_as_uint(As[(ar + mt * 16 + 8) * AST + ac]);
                a[mt][2] = __float_as_uint(As[(ar + mt * 16) * AST + ac + 4]);
                a[mt][3] = __float_as_uint(As[(ar + mt * 16 + 8) * AST + ac + 4]);
            }
            #pragma unroll
            for (int nt = 0; nt < 8; nt++) {
                uint32_t b[2];
                const int bn = wc * 64 + nt * 8 + g;
                const int bk = ks * 8 + tg;
                b[0] = __float_as_uint(Bs[bk * BST + bn]);
                b[1] = __float_as_uint(Bs[(bk + 4) * BST + bn]);
                mma_tf32(C[0][nt], a[0], b);
                mma_tf32(C[1][nt], a[1], b);
            }
        }
        __syncthreads();
    }

    float bb1[8][2], ww2[8][2];
    #pragma unroll
    for (int nt = 0; nt < 8; nt++) {
        int n0 = wc * 64 + nt * 8 + tg * 2;
        bb1[nt][0] = __ldg(&b1[n0]);     bb1[nt][1] = __ldg(&b1[n0 + 1]);
        ww2[nt][0] = __ldg(&w2[n0]);     ww2[nt][1] = __ldg(&w2[n0 + 1]);
    }
    float part[2][2];
    part[0][0] = part[0][1] = part[1][0] = part[1][1] = 0.f;
    #pragma unroll
    for (int mt = 0; mt < 2; mt++)
        #pragma unroll
        for (int nt = 0; nt < 8; nt++) {
            part[mt][0] = fmaf(fmaxf(C[mt][nt][0] + bb1[nt][0], 0.f), ww2[nt][0], part[mt][0]);
            part[mt][0] = fmaf(fmaxf(C[mt][nt][1] + bb1[nt][1], 0.f), ww2[nt][1], part[mt][0]);
            part[mt][1] = fmaf(fmaxf(C[mt][nt][2] + bb1[nt][0], 0.f), ww2[nt][0], part[mt][1]);
            part[mt][1] = fmaf(fmaxf(C[mt][nt][3] + bb1[nt][1], 0.f), ww2[nt][1], part[mt][1]);
        }
    __syncthreads();
    float* red = As;
    #pragma unroll
    for (int mt = 0; mt < 2; mt++) {
        int r0 = wr * 32 + mt * 16 + g;
        red[r0 * 16 + wc * 4 + tg]       = part[mt][0];
        red[(r0 + 8) * 16 + wc * 4 + tg] = part[mt][1];
    }
    __syncthreads();
    if (tid < BM) {
        float s = 0.f;
        #pragma unroll
        for (int i = 0; i < 16; i++) s += red[tid * 16 + i];
        s += __ldg(&b2[0]);
        g_weights[m0 + tid] = 1.f / (1.f + expf(-s));
    }
}

// ---------------- Kmain: 256 blocks x 64 rows (4 iters of 16 warps) ------
__global__ __launch_bounds__(512)
void kmain(const float* __restrict__ feat,
           float* __restrict__ out_refined,
           float* __restrict__ out_att) {
    __shared__ float sA[An * Dn];
    __shared__ float sW[(An + 1) * Dn];
    __shared__ float sn2[An];
    __shared__ float red[16];
    const int tid = threadIdx.x;
    for (int i = tid; i < An * Dn; i += 512) sA[i] = g_anch[i];
    for (int i = tid; i < (An + 1) * Dn; i += 512) sW[i] = g_anchVW[i];
    if (tid < An) sn2[tid] = g_an2[tid];
    __syncthreads();

    const int wid = tid >> 5, l = tid & 31;
    float cp_acc = 0.f;

    #pragma unroll 1
    for (int it = 0; it < 4; it++) {
        const int r = blockIdx.x * 64 + it * 16 + wid;
        const float* f = feat + (size_t)r * Dn;

        float4 fv[4];
        #pragma unroll
        for (int j = 0; j < 4; j++) fv[j] = *(const float4*)&f[j * 128 + l * 4];

        float v11[11];
        {
            float s = 0.f;
            #pragma unroll
            for (int j = 0; j < 4; j++) {
                s = fmaf(fv[j].x, fv[j].x, s); s = fmaf(fv[j].y, fv[j].y, s);
                s = fmaf(fv[j].z, fv[j].z, s); s = fmaf(fv[j].w, fv[j].w, s);
            }
            v11[10] = s;
        }
        #pragma unroll
        for (int a = 0; a < An; a++) {
            float d = 0.f;
            #pragma unroll
            for (int j = 0; j < 4; j++) {
                float4 av = *(const float4*)&sA[a * Dn + j * 128 + l * 4];
                d = fmaf(fv[j].x, av.x, d); d = fmaf(fv[j].y, av.y, d);
                d = fmaf(fv[j].z, av.z, d); d = fmaf(fv[j].w, av.w, d);
            }
            v11[a] = d;
        }
        #pragma unroll
        for (int a = 0; a < 11; a++) {
            #pragma unroll
            for (int o = 16; o; o >>= 1) v11[a] += __shfl_xor_sync(0xffffffffu, v11[a], o);
        }

        const float fn2 = v11[10];
        const float inv_temp = rsqrtf(fn2);
        float att[An];
        float mx = -1e30f;
        #pragma unroll
        for (int a = 0; a < An; a++) {
            float d2 = fn2 - 2.f * v11[a] + sn2[a];
            float dist = sqrtf(fmaxf(d2, 0.f));
            float lg = -dist * inv_temp;
            att[a] = lg;
            mx = fmaxf(mx, lg);
        }
        float se = 0.f;
        #pragma unroll
        for (int a = 0; a < An; a++) { att[a] = __expf(att[a] - mx); se += att[a]; }
        const float inv_se = 1.f / se;
        #pragma unroll
        for (int a = 0; a < An; a++) att[a] *= inv_se;

        const float w = g_weights[r];

        float cp = 0.f;
        #pragma unroll
        for (int j = 0; j < 4; j++) {
            int base = j * 128 + l * 4;
            float4 cb = *(const float4*)&sW[An * Dn + base];
            float4 ac = make_float4(0.f, 0.f, 0.f, 0.f);
            #pragma unroll
            for (int a = 0; a < An; a++) {
                float4 av = *(const float4*)&sW[a * Dn + base];
                ac.x = fmaf(att[a], av.x, ac.x); ac.y = fmaf(att[a], av.y, ac.y);
                ac.z = fmaf(att[a], av.z, ac.z); ac.w = fmaf(att[a], av.w, ac.w);
            }
            float4 rr;
            rr.x = fmaf(w, ac.x, cb.x); rr.y = fmaf(w, ac.y, cb.y);
            rr.z = fmaf(w, ac.z, cb.z); rr.w = fmaf(w, ac.w, cb.w);
            *(float4*)&out_refined[(size_t)r * Dn + base] = rr;
            float dx = fv[j].x - rr.x; cp = fmaf(dx, dx, cp);
            dx = fv[j].y - rr.y; cp = fmaf(dx, dx, cp);
            dx = fv[j].z - rr.z; cp = fmaf(dx, dx, cp);
            dx = fv[j].w - rr.w; cp = fmaf(dx, dx, cp);
        }

        #pragma unroll
        for (int a = 0; a < An; a++)
            if (l == a) out_att[(size_t)r * An + a] = att[a];

        cp_acc += cp;
    }

    #pragma unroll
    for (int o = 16; o; o >>= 1) cp_acc += __shfl_xor_sync(0xffffffffu, cp_acc, o);
    if (l == 0) red[wid] = cp_acc;
    __syncthreads();
    if (tid == 0) {
        float t = 0.f;
        #pragma unroll
        for (int i = 0; i < 16; i++) t += red[i];
        g_partials[blockIdx.x] = t;
    }
}

// ---------------- Kfinal: total_loss (parallel, deterministic) -----------
__global__ void kfinal(const float* __restrict__ anchors,
                       const float* __restrict__ clw,
                       float* __restrict__ out_scalar) {
    __shared__ float sm[32];
    const int tid = threadIdx.x;  // 512
    const int w = tid >> 5, l = tid & 31;

    float s = (tid < KMAIN_BLOCKS) ? g_partials[tid] : 0.f;
    #pragma unroll
    for (int o = 16; o; o >>= 1) s += __shfl_xor_sync(0xffffffffu, s, o);
    if (l == 0) sm[w] = s;

    float pd = 0.f;
    #pragma unroll
    for (int pp = 0; pp < 3; pp++) {
        int p = w + pp * 16;
        if (p < 45) {  // warp-uniform
            int i = 0, q = p;
            while (q >= 9 - i) { q -= 9 - i; i++; }
            int j = i + 1 + q;
            float ss = 0.f;
            #pragma unroll
            for (int dd = 0; dd < 16; dd++) {
                float df = anchors[i * Dn + dd * 32 + l] -
                           anchors[j * Dn + dd * 32 + l];
                ss = fmaf(df, df, ss);
            }
            #pragma unroll
            for (int o = 16; o; o >>= 1) ss += __shfl_xor_sync(0xffffffffu, ss, o);
            pd += sqrtf(fmaxf(ss, 0.f));
        }
    }
    if (l == 0) sm[16 + w] = pd;
    __syncthreads();
    if (tid == 0) {
        float c = 0.f, d = 0.f;
        #pragma unroll
        for (int i = 0; i < 16; i++) { c += sm[i]; d += sm[16 + i]; }
        float center = c * (1.f / (float)Bn);
        float div = -(d / 45.f);
        out_scalar[0] = clw[0] * center + 0.1f * div;
    }
}

// ---------------- launch ----------------
extern "C" void kernel_launch(void* const* d_in, const int* in_sizes, int n_in,
                              void* d_out, int out_size) {
    const float* features = (const float*)d_in[0];
    const float* anchors  = (const float*)d_in[1];
    const float* pos      = (const float*)d_in[2];
    const float* qkv_w    = (const float*)d_in[3];
    const float* qkv_b    = (const float*)d_in[4];
    const float* proj_w   = (const float*)d_in[5];
    const float* proj_b   = (const float*)d_in[6];
    const float* w1       = (const float*)d_in[7];
    const float* b1       = (const float*)d_in[8];
    const float* w2       = (const float*)d_in[9];
    const float* b2       = (const float*)d_in[10];
    const float* clw      = (const float*)d_in[11];

    float* out         = (float*)d_out;
    float* out_refined = out;                        // B*D
    float* out_scalar  = out + (size_t)Bn * Dn;      // 1
    float* out_att     = out + (size_t)Bn * Dn + 1;  // B*A

    kgemm_weights<<<Bn / BM, 512>>>(features, w1, b1, w2, b2);
    k0_setup<<<1, 512>>>(anchors, pos);
    k1_part<<<dim3(2, KSPLIT), 256>>>(qkv_w);
    k1_reduce<<<An + 1, 512>>>(qkv_b);
    k2_part<<<dim3(2, KSPLIT), 256>>>(proj_w);
    k2_reduce<<<An + 1, 512>>>(proj_b);
    kmain<<<KMAIN_BLOCKS, 512>>>(features, out_refined, out_att);
    kfinal<<<1, 512>>>(anchors, clw, out_scalar);
}

// round 7
// speedup vs baseline: 1.3864x; 1.0685x over previous
#include <cuda_runtime.h>
#include <math.h>
#include <stdint.h>

#define Bn 16384
#define Dn 512
#define An 10
#define KMAIN_BLOCKS 256
#define KSPLIT 8          // k-chunks for k1/k2 partials
#define KCH (Dn / KSPLIT) // 64

// ---------------- scratch (no allocations allowed) ----------------
__device__ float g_anch[An * Dn];             // anchors + pos_embedding
__device__ float g_an2[An];                   // ||anch[a]||^2
__device__ float g_part[KSPLIT * (An + 1) * Dn];   // k1 partials
__device__ float g_part2[KSPLIT * (An + 1) * Dn];  // k2 partials
__device__ float g_anchVW[(An + 1) * Dn];     // (anch@Wv)@proj_w ; row10 = cbias
__device__ float g_weights[Bn];               // sigmoid gate per row
__device__ float g_partials[KMAIN_BLOCKS];    // center-loss per-block partials

// ---------------- K0: anch = anchors + pos ; ||anch||^2 ----------------
__global__ void k0_setup(const float* __restrict__ anchors,
                         const float* __restrict__ pos) {
    int t = threadIdx.x;  // 512
    for (int i = t; i < An * Dn; i += 512) g_anch[i] = anchors[i] + pos[i];
    __syncthreads();
    int w = t >> 5, l = t & 31;
    if (w < An) {
        float s = 0.f;
        for (int k = l; k < Dn; k += 32) {
            float v = g_anch[w * Dn + k];
            s = fmaf(v, v, s);
        }
        #pragma unroll
        for (int o = 16; o; o >>= 1) s += __shfl_xor_sync(0xffffffffu, s, o);
        if (l == 0) g_an2[w] = s;
    }
}

// ---------------- K1 part: partial anchV over a k-chunk (coalesced) ------
__global__ void k1_part(const float* __restrict__ qkv_w) {
    __shared__ float sa[An * KCH];
    const int tid = threadIdx.x;
    const int kc = blockIdx.y, k0 = kc * KCH;
    const int j = blockIdx.x * 256 + tid;
    for (int i = tid; i < An * KCH; i += 256) {
        int a = i / KCH, k = i % KCH;
        sa[i] = g_anch[a * Dn + k0 + k];
    }
    __syncthreads();
    float acc[An];
    #pragma unroll
    for (int a = 0; a < An; a++) acc[a] = 0.f;
    #pragma unroll 8
    for (int k = 0; k < KCH; k++) {
        float w = __ldg(&qkv_w[(size_t)(k0 + k) * (3 * Dn) + 2 * Dn + j]);
        #pragma unroll
        for (int a = 0; a < An; a++) acc[a] = fmaf(sa[a * KCH + k], w, acc[a]);
    }
    #pragma unroll
    for (int a = 0; a < An; a++)
        g_part[kc * ((An + 1) * Dn) + a * Dn + j] = acc[a];
}

// ---------------- K2 part: fuses k1-reduce into the smem staging ---------
// sa[a][k] = sum_kc k1partial (a<An) ; qkv_b_v slice (a==An).
__global__ void k2_part(const float* __restrict__ proj_w,
                        const float* __restrict__ qkv_b) {
    __shared__ float sa[(An + 1) * KCH];
    const int tid = threadIdx.x;
    const int kc = blockIdx.y, k0 = kc * KCH;
    const int d = blockIdx.x * 256 + tid;
    for (int i = tid; i < (An + 1) * KCH; i += 256) {
        int a = i / KCH, k = i % KCH;
        float v;
        if (a == An) {
            v = qkv_b[2 * Dn + k0 + k];
        } else {
            v = 0.f;
            #pragma unroll
            for (int c = 0; c < KSPLIT; c++)
                v += g_part[c * ((An + 1) * Dn) + a * Dn + k0 + k];
        }
        sa[i] = v;
    }
    __syncthreads();
    float acc[An + 1];
    #pragma unroll
    for (int a = 0; a <= An; a++) acc[a] = 0.f;
    #pragma unroll 8
    for (int k = 0; k < KCH; k++) {
        float w = __ldg(&proj_w[(size_t)(k0 + k) * Dn + d]);
        #pragma unroll
        for (int a = 0; a <= An; a++) acc[a] = fmaf(sa[a * KCH + k], w, acc[a]);
    }
    #pragma unroll
    for (int a = 0; a <= An; a++)
        g_part2[kc * ((An + 1) * Dn) + a * Dn + d] = acc[a];
}

// ---------------- K2 reduce: sum partials ; row10 += proj_b --------------
__global__ void k2_reduce(const float* __restrict__ proj_b) {
    const int a = blockIdx.x;
    const int d = threadIdx.x;
    float s = 0.f;
    #pragma unroll
    for (int kc = 0; kc < KSPLIT; kc++)
        s += g_part2[kc * ((An + 1) * Dn) + a * Dn + d];
    if (a == An) s += proj_b[d];
    g_anchVW[a * Dn + d] = s;
}

// ---------------- Kgemm: weights = sigmoid(relu(F@w1+b1)@w2+b2) ----------
// tf32 mma.sync m16n8k8, cp.async double-buffered.
// BM=64, BN=256, BK=16, 512 threads = 16 warps (4 rowgrp x 4 colgrp), warp 16x64.
// Smem: 2*(64*20 + 16*264)*4 = 43.0KB static.
#define BMg 64
#define BKg 16
#define AST 20    // As row stride: (g*20+tg) mod 32 distinct over warp
#define BST 264   // Bs row stride: (tg*8+g) covers banks 0..31

__device__ __forceinline__ void mma_tf32(float c[4], const uint32_t a[4],
                                         const uint32_t b[2]) {
    asm volatile(
        "mma.sync.aligned.m16n8k8.row.col.f32.tf32.tf32.f32 "
        "{%0,%1,%2,%3}, {%4,%5,%6,%7}, {%8,%9}, {%0,%1,%2,%3};"
        : "+f"(c[0]), "+f"(c[1]), "+f"(c[2]), "+f"(c[3])
        : "r"(a[0]), "r"(a[1]), "r"(a[2]), "r"(a[3]), "r"(b[0]), "r"(b[1]));
}

__device__ __forceinline__ void cp16(uint32_t dst, const float* src) {
    asm volatile("cp.async.ca.shared.global [%0], [%1], 16;\n"
                 :: "r"(dst), "l"(src));
}
__device__ __forceinline__ void cp_commit() {
    asm volatile("cp.async.commit_group;\n" ::: "memory");
}
template <int N>
__device__ __forceinline__ void cp_wait() {
    asm volatile("cp.async.wait_group %0;\n" :: "n"(N) : "memory");
}

__global__ __launch_bounds__(512)
void kgemm_weights(const float* __restrict__ f,
                   const float* __restrict__ w1,
                   const float* __restrict__ b1v,
                   const float* __restrict__ w2,
                   const float* __restrict__ b2) {
    __shared__ float As[2][BMg * AST];   // 2 x 5.0KB
    __shared__ float Bs[2][BKg * BST];   // 2 x 16.5KB
    const int tid = threadIdx.x;
    const int wid = tid >> 5, l = tid & 31;
    const int wr = wid & 3;              // rows wr*16..+16
    const int wc = wid >> 2;             // cols wc*64..+64
    const int g = l >> 2, tg = l & 3;
    const int m0 = blockIdx.x * BMg;

    const uint32_t sA0 = (uint32_t)__cvta_generic_to_shared(&As[0][0]);
    const uint32_t sA1 = (uint32_t)__cvta_generic_to_shared(&As[1][0]);
    const uint32_t sB0 = (uint32_t)__cvta_generic_to_shared(&Bs[0][0]);
    const uint32_t sB1 = (uint32_t)__cvta_generic_to_shared(&Bs[1][0]);

    // per-thread cp.async assignments
    const int arow = tid >> 2, ac4 = tid & 3;          // A: tid<256
    const int bkr0 = tid >> 6, bn40 = tid & 63;        // B chunk 0
    const int bkr1 = (tid + 512) >> 6, bn41 = tid & 63;// B chunk 1

    #define ISSUE_STAGE(s) do {                                              \
        int _buf = (s) & 1; int _k0 = (s) * BKg;                             \
        uint32_t _a = _buf ? sA1 : sA0, _b = _buf ? sB1 : sB0;               \
        if (tid < 256)                                                       \
            cp16(_a + (arow * AST + ac4 * 4) * 4,                            \
                 &f[(size_t)(m0 + arow) * Dn + _k0 + ac4 * 4]);              \
        cp16(_b + (bkr0 * BST + bn40 * 4) * 4,                               \
             &w1[(size_t)(_k0 + bkr0) * 256 + bn40 * 4]);                    \
        cp16(_b + (bkr1 * BST + bn41 * 4) * 4,                               \
             &w1[(size_t)(_k0 + bkr1) * 256 + bn41 * 4]);                    \
        cp_commit();                                                         \
    } while (0)

    float C[8][4];
    #pragma unroll
    for (int nt = 0; nt < 8; nt++)
        #pragma unroll
        for (int i = 0; i < 4; i++) C[nt][i] = 0.f;

    ISSUE_STAGE(0);
    ISSUE_STAGE(1);

    const int NIT = Dn / BKg;  // 32
    for (int it = 0; it < NIT; it++) {
        cp_wait<1>();
        __syncthreads();
        const float* Ab = As[it & 1];
        const float* Bb = Bs[it & 1];
        #pragma unroll
        for (int ks = 0; ks < 2; ks++) {
            uint32_t a[4];
            const int ar = wr * 16 + g;
            const int acl = ks * 8 + tg;
            a[0] = __float_as_uint(Ab[ar * AST + acl]);
            a[1] = __float_as_uint(Ab[(ar + 8) * AST + acl]);
            a[2] = __float_as_uint(Ab[ar * AST + acl + 4]);
            a[3] = __float_as_uint(Ab[(ar + 8) * AST + acl + 4]);
            #pragma unroll
            for (int nt = 0; nt < 8; nt++) {
                uint32_t rb[2];
                const int bn = wc * 64 + nt * 8 + g;
                const int bk = ks * 8 + tg;
                rb[0] = __float_as_uint(Bb[bk * BST + bn]);
                rb[1] = __float_as_uint(Bb[(bk + 4) * BST + bn]);
                mma_tf32(C[nt], a, rb);
            }
        }
        __syncthreads();
        if (it + 2 < NIT) ISSUE_STAGE(it + 2);
    }

    // epilogue: relu(+b1), dot w2 over this thread's 16 cols; 2 rows
    float p0 = 0.f, p1 = 0.f;
    #pragma unroll
    for (int nt = 0; nt < 8; nt++) {
        int n0 = wc * 64 + nt * 8 + tg * 2;
        float bb0 = __ldg(&b1v[n0]), bb1 = __ldg(&b1v[n0 + 1]);
        float wv0 = __ldg(&w2[n0]),  wv1 = __ldg(&w2[n0 + 1]);
        p0 = fmaf(fmaxf(C[nt][0] + bb0, 0.f), wv0, p0);
        p0 = fmaf(fmaxf(C[nt][1] + bb1, 0.f), wv1, p0);
        p1 = fmaf(fmaxf(C[nt][2] + bb0, 0.f), wv0, p1);
        p1 = fmaf(fmaxf(C[nt][3] + bb1, 0.f), wv1, p1);
    }
    __syncthreads();
    float* red = &As[0][0];  // 64 rows x 16 slots = 4KB
    {
        int r0 = wr * 16 + g;
        red[r0 * 16 + wc * 4 + tg]       = p0;
        red[(r0 + 8) * 16 + wc * 4 + tg] = p1;
    }
    __syncthreads();
    if (tid < BMg) {
        float s = 0.f;
        #pragma unroll
        for (int i = 0; i < 16; i++) s += red[tid * 16 + i];
        s += __ldg(&b2[0]);
        g_weights[m0 + tid] = 1.f / (1.f + expf(-s));
    }
    #undef ISSUE_STAGE
}

// ---------------- Kmain: 256 blocks x 64 rows (4 iters of 16 warps) ------
__global__ __launch_bounds__(512)
void kmain(const float* __restrict__ feat,
           float* __restrict__ out_refined,
           float* __restrict__ out_att) {
    __shared__ float sA[An * Dn];
    __shared__ float sW[(An + 1) * Dn];
    __shared__ float sn2[An];
    __shared__ float red[16];
    const int tid = threadIdx.x;
    for (int i = tid; i < An * Dn; i += 512) sA[i] = g_anch[i];
    for (int i = tid; i < (An + 1) * Dn; i += 512) sW[i] = g_anchVW[i];
    if (tid < An) sn2[tid] = g_an2[tid];
    __syncthreads();

    const int wid = tid >> 5, l = tid & 31;
    float cp_acc = 0.f;

    #pragma unroll 1
    for (int it = 0; it < 4; it++) {
        const int r = blockIdx.x * 64 + it * 16 + wid;
        const float* f = feat + (size_t)r * Dn;

        float4 fv[4];
        #pragma unroll
        for (int j = 0; j < 4; j++) fv[j] = *(const float4*)&f[j * 128 + l * 4];

        float v11[11];
        {
            float s = 0.f;
            #pragma unroll
            for (int j = 0; j < 4; j++) {
                s = fmaf(fv[j].x, fv[j].x, s); s = fmaf(fv[j].y, fv[j].y, s);
                s = fmaf(fv[j].z, fv[j].z, s); s = fmaf(fv[j].w, fv[j].w, s);
            }
            v11[10] = s;
        }
        #pragma unroll
        for (int a = 0; a < An; a++) {
            float d = 0.f;
            #pragma unroll
            for (int j = 0; j < 4; j++) {
                float4 av = *(const float4*)&sA[a * Dn + j * 128 + l * 4];
                d = fmaf(fv[j].x, av.x, d); d = fmaf(fv[j].y, av.y, d);
                d = fmaf(fv[j].z, av.z, d); d = fmaf(fv[j].w, av.w, d);
            }
            v11[a] = d;
        }
        #pragma unroll
        for (int a = 0; a < 11; a++) {
            #pragma unroll
            for (int o = 16; o; o >>= 1) v11[a] += __shfl_xor_sync(0xffffffffu, v11[a], o);
        }

        const float fn2 = v11[10];
        const float inv_temp = rsqrtf(fn2);
        float att[An];
        float mx = -1e30f;
        #pragma unroll
        for (int a = 0; a < An; a++) {
            float d2 = fn2 - 2.f * v11[a] + sn2[a];
            float dist = sqrtf(fmaxf(d2, 0.f));
            float lg = -dist * inv_temp;
            att[a] = lg;
            mx = fmaxf(mx, lg);
        }
        float se = 0.f;
        #pragma unroll
        for (int a = 0; a < An; a++) { att[a] = __expf(att[a] - mx); se += att[a]; }
        const float inv_se = 1.f / se;
        #pragma unroll
        for (int a = 0; a < An; a++) att[a] *= inv_se;

        const float w = g_weights[r];

        float cp = 0.f;
        #pragma unroll
        for (int j = 0; j < 4; j++) {
            int base = j * 128 + l * 4;
            float4 cb = *(const float4*)&sW[An * Dn + base];
            float4 ac = make_float4(0.f, 0.f, 0.f, 0.f);
            #pragma unroll
            for (int a = 0; a < An; a++) {
                float4 av = *(const float4*)&sW[a * Dn + base];
                ac.x = fmaf(att[a], av.x, ac.x); ac.y = fmaf(att[a], av.y, ac.y);
                ac.z = fmaf(att[a], av.z, ac.z); ac.w = fmaf(att[a], av.w, ac.w);
            }
            float4 rr;
            rr.x = fmaf(w, ac.x, cb.x); rr.y = fmaf(w, ac.y, cb.y);
            rr.z = fmaf(w, ac.z, cb.z); rr.w = fmaf(w, ac.w, cb.w);
            *(float4*)&out_refined[(size_t)r * Dn + base] = rr;
            float dx = fv[j].x - rr.x; cp = fmaf(dx, dx, cp);
            dx = fv[j].y - rr.y; cp = fmaf(dx, dx, cp);
            dx = fv[j].z - rr.z; cp = fmaf(dx, dx, cp);
            dx = fv[j].w - rr.w; cp = fmaf(dx, dx, cp);
        }

        #pragma unroll
        for (int a = 0; a < An; a++)
            if (l == a) out_att[(size_t)r * An + a] = att[a];

        cp_acc += cp;
    }

    #pragma unroll
    for (int o = 16; o; o >>= 1) cp_acc += __shfl_xor_sync(0xffffffffu, cp_acc, o);
    if (l == 0) red[wid] = cp_acc;
    __syncthreads();
    if (tid == 0) {
        float t = 0.f;
        #pragma unroll
        for (int i = 0; i < 16; i++) t += red[i];
        g_partials[blockIdx.x] = t;
    }
}

// ---------------- Kfinal: total_loss (parallel, deterministic) -----------
__global__ void kfinal(const float* __restrict__ anchors,
                       const float* __restrict__ clw,
                       float* __restrict__ out_scalar) {
    __shared__ float sm[32];
    const int tid = threadIdx.x;  // 512
    const int w = tid >> 5, l = tid & 31;

    float s = (tid < KMAIN_BLOCKS) ? g_partials[tid] : 0.f;
    #pragma unroll
    for (int o = 16; o; o >>= 1) s += __shfl_xor_sync(0xffffffffu, s, o);
    if (l == 0) sm[w] = s;

    float pd = 0.f;
    #pragma unroll
    for (int pp = 0; pp < 3; pp++) {
        int p = w + pp * 16;
        if (p < 45) {  // warp-uniform
            int i = 0, q = p;
            while (q >= 9 - i) { q -= 9 - i; i++; }
            int j = i + 1 + q;
            float ss = 0.f;
            #pragma unroll
            for (int dd = 0; dd < 16; dd++) {
                float df = anchors[i * Dn + dd * 32 + l] -
                           anchors[j * Dn + dd * 32 + l];
                ss = fmaf(df, df, ss);
            }
            #pragma unroll
            for (int o = 16; o; o >>= 1) ss += __shfl_xor_sync(0xffffffffu, ss, o);
            pd += sqrtf(fmaxf(ss, 0.f));
        }
    }
    if (l == 0) sm[16 + w] = pd;
    __syncthreads();
    if (tid == 0) {
        float c = 0.f, d = 0.f;
        #pragma unroll
        for (int i = 0; i < 16; i++) { c += sm[i]; d += sm[16 + i]; }
        float center = c * (1.f / (float)Bn);
        float div = -(d / 45.f);
        out_scalar[0] = clw[0] * center + 0.1f * div;
    }
}

// ---------------- launch (kgemm at index 3 = the ncu capture slot) -------
extern "C" void kernel_launch(void* const* d_in, const int* in_sizes, int n_in,
                              void* d_out, int out_size) {
    const float* features = (const float*)d_in[0];
    const float* anchors  = (const float*)d_in[1];
    const float* pos      = (const float*)d_in[2];
    const float* qkv_w    = (const float*)d_in[3];
    const float* qkv_b    = (const float*)d_in[4];
    const float* proj_w   = (const float*)d_in[5];
    const float* proj_b   = (const float*)d_in[6];
    const float* w1       = (const float*)d_in[7];
    const float* b1       = (const float*)d_in[8];
    const float* w2       = (const float*)d_in[9];
    const float* b2       = (const float*)d_in[10];
    const float* clw      = (const float*)d_in[11];

    float* out         = (float*)d_out;
    float* out_refined = out;                        // B*D
    float* out_scalar  = out + (size_t)Bn * Dn;      // 1
    float* out_att     = out + (size_t)Bn * Dn + 1;  // B*A

    k0_setup<<<1, 512>>>(anchors, pos);                      // 0
    k1_part<<<dim3(2, KSPLIT), 256>>>(qkv_w);                // 1
    k2_part<<<dim3(2, KSPLIT), 256>>>(proj_w, qkv_b);        // 2
    kgemm_weights<<<Bn / BMg, 512>>>(features, w1, b1, w2, b2); // 3 <- profiled
    k2_reduce<<<An + 1, 512>>>(proj_b);                      // 4
    kmain<<<KMAIN_BLOCKS, 512>>>(features, out_refined, out_att); // 5
    kfinal<<<1, 512>>>(anchors, clw, out_scalar);            // 6
}

// round 8
// speedup vs baseline: 1.5062x; 1.0864x over previous
#include <cuda_runtime.h>
#include <math.h>
#include <stdint.h>

#define Bn 16384
#define Dn 512
#define An 10
#define KMAIN_BLOCKS 256
#define KSPLIT 8          // k-chunks for k1/k2 partials
#define KCH (Dn / KSPLIT) // 64

// ---------------- scratch (no allocations allowed) ----------------
__device__ float g_part[KSPLIT * (An + 1) * Dn];   // k1 partials
__device__ float g_part2[KSPLIT * (An + 1) * Dn];  // k2 partials
__device__ float g_anchVW[(An + 1) * Dn];     // (anch@Wv)@proj_w ; row10 = cbias
__device__ float g_weights[Bn];               // sigmoid gate per row
__device__ float g_partials[KMAIN_BLOCKS];    // center-loss per-block partials
__device__ int   g_ticket;                    // last-block ticket (reset each run)

// ---------------- K1 part: partial anchV over a k-chunk ------------------
// anch computed inline (anchors + pos). grid (2, KSPLIT), 256 threads.
__global__ void k1_part(const float* __restrict__ qkv_w,
                        const float* __restrict__ anchors,
                        const float* __restrict__ pos) {
    __shared__ float sa[An * KCH];
    const int tid = threadIdx.x;
    const int kc = blockIdx.y, k0 = kc * KCH;
    const int j = blockIdx.x * 256 + tid;
    for (int i = tid; i < An * KCH; i += 256) {
        int a = i / KCH, k = i % KCH;
        int gi = a * Dn + k0 + k;
        sa[i] = anchors[gi] + pos[gi];
    }
    __syncthreads();
    float acc[An];
    #pragma unroll
    for (int a = 0; a < An; a++) acc[a] = 0.f;
    #pragma unroll 8
    for (int k = 0; k < KCH; k++) {
        float w = __ldg(&qkv_w[(size_t)(k0 + k) * (3 * Dn) + 2 * Dn + j]);
        #pragma unroll
        for (int a = 0; a < An; a++) acc[a] = fmaf(sa[a * KCH + k], w, acc[a]);
    }
    #pragma unroll
    for (int a = 0; a < An; a++)
        g_part[kc * ((An + 1) * Dn) + a * Dn + j] = acc[a];
}

// ---------------- K2 part: fuses k1-reduce into the smem staging ---------
__global__ void k2_part(const float* __restrict__ proj_w,
                        const float* __restrict__ qkv_b) {
    __shared__ float sa[(An + 1) * KCH];
    const int tid = threadIdx.x;
    const int kc = blockIdx.y, k0 = kc * KCH;
    const int d = blockIdx.x * 256 + tid;
    for (int i = tid; i < (An + 1) * KCH; i += 256) {
        int a = i / KCH, k = i % KCH;
        float v;
        if (a == An) {
            v = qkv_b[2 * Dn + k0 + k];
        } else {
            v = 0.f;
            #pragma unroll
            for (int c = 0; c < KSPLIT; c++)
                v += g_part[c * ((An + 1) * Dn) + a * Dn + k0 + k];
        }
        sa[i] = v;
    }
    __syncthreads();
    float acc[An + 1];
    #pragma unroll
    for (int a = 0; a <= An; a++) acc[a] = 0.f;
    #pragma unroll 8
    for (int k = 0; k < KCH; k++) {
        float w = __ldg(&proj_w[(size_t)(k0 + k) * Dn + d]);
        #pragma unroll
        for (int a = 0; a <= An; a++) acc[a] = fmaf(sa[a * KCH + k], w, acc[a]);
    }
    #pragma unroll
    for (int a = 0; a <= An; a++)
        g_part2[kc * ((An + 1) * Dn) + a * Dn + d] = acc[a];
}

// ---------------- Kgemm: weights + fused k2_reduce -----------------------
// tf32 mma.sync m16n8k8, cp.async double-buffered.
// BM=64, BN=256, BK=16, 256 threads = 8 warps (2 rowgrp x 4 colgrp), warp 32x64.
#define BMg 64
#define BKg 16
#define AST 20
#define BST 264

__device__ __forceinline__ void mma_tf32(float c[4], const uint32_t a[4],
                                         const uint32_t b[2]) {
    asm volatile(
        "mma.sync.aligned.m16n8k8.row.col.f32.tf32.tf32.f32 "
        "{%0,%1,%2,%3}, {%4,%5,%6,%7}, {%8,%9}, {%0,%1,%2,%3};"
        : "+f"(c[0]), "+f"(c[1]), "+f"(c[2]), "+f"(c[3])
        : "r"(a[0]), "r"(a[1]), "r"(a[2]), "r"(a[3]), "r"(b[0]), "r"(b[1]));
}

__device__ __forceinline__ void cp16(uint32_t dst, const float* src) {
    asm volatile("cp.async.ca.shared.global [%0], [%1], 16;\n"
                 :: "r"(dst), "l"(src));
}
__device__ __forceinline__ void cp_commit() {
    asm volatile("cp.async.commit_group;\n" ::: "memory");
}
template <int N>
__device__ __forceinline__ void cp_wait() {
    asm volatile("cp.async.wait_group %0;\n" :: "n"(N) : "memory");
}

__global__ __launch_bounds__(256)
void kgemm_weights(const float* __restrict__ f,
                   const float* __restrict__ w1,
                   const float* __restrict__ b1v,
                   const float* __restrict__ w2,
                   const float* __restrict__ b2,
                   const float* __restrict__ proj_b) {
    __shared__ float As[2][BMg * AST];   // 2 x 5.0KB
    __shared__ float Bs[2][BKg * BST];   // 2 x 16.5KB
    const int tid = threadIdx.x;
    const int wid = tid >> 5, l = tid & 31;
    const int wr = wid & 1;              // rows wr*32..+32
    const int wc = wid >> 1;             // cols wc*64..+64
    const int g = l >> 2, tg = l & 3;
    const int m0 = blockIdx.x * BMg;

    // fused k2_reduce: blocks 0..An finalize anchVW row blockIdx.x
    if (blockIdx.x <= An) {
        const int a = blockIdx.x;
        for (int d = tid; d < Dn; d += 256) {
            float s = 0.f;
            #pragma unroll
            for (int kc = 0; kc < KSPLIT; kc++)
                s += g_part2[kc * ((An + 1) * Dn) + a * Dn + d];
            if (a == An) s += proj_b[d];
            g_anchVW[a * Dn + d] = s;
        }
    }

    const uint32_t sA0 = (uint32_t)__cvta_generic_to_shared(&As[0][0]);
    const uint32_t sA1 = (uint32_t)__cvta_generic_to_shared(&As[1][0]);
    const uint32_t sB0 = (uint32_t)__cvta_generic_to_shared(&Bs[0][0]);
    const uint32_t sB1 = (uint32_t)__cvta_generic_to_shared(&Bs[1][0]);

    const int arow = tid >> 2, ac4 = tid & 3;  // A: 1 float4 per thread

    #define ISSUE_STAGE(s) do {                                              \
        int _buf = (s) & 1; int _k0 = (s) * BKg;                             \
        uint32_t _a = _buf ? sA1 : sA0, _b = _buf ? sB1 : sB0;               \
        cp16(_a + (arow * AST + ac4 * 4) * 4,                                \
             &f[(size_t)(m0 + arow) * Dn + _k0 + ac4 * 4]);                  \
        _Pragma("unroll")                                                    \
        for (int _p = 0; _p < 4; _p++) {                                     \
            int _idx = tid + _p * 256;                                       \
            int _kr = _idx >> 6, _n4 = _idx & 63;                            \
            cp16(_b + (_kr * BST + _n4 * 4) * 4,                             \
                 &w1[(size_t)(_k0 + _kr) * 256 + _n4 * 4]);                  \
        }                                                                    \
        cp_commit();                                                         \
    } while (0)

    float C[2][8][4];
    #pragma unroll
    for (int mt = 0; mt < 2; mt++)
        #pragma unroll
        for (int nt = 0; nt < 8; nt++)
            #pragma unroll
            for (int i = 0; i < 4; i++) C[mt][nt][i] = 0.f;

    ISSUE_STAGE(0);
    ISSUE_STAGE(1);

    const int NIT = Dn / BKg;  // 32
    for (int it = 0; it < NIT; it++) {
        cp_wait<1>();
        __syncthreads();
        const float* Ab = As[it & 1];
        const float* Bb = Bs[it & 1];
        #pragma unroll
        for (int ks = 0; ks < 2; ks++) {
            uint32_t a[2][4];
            const int acl = ks * 8 + tg;
            #pragma unroll
            for (int mt = 0; mt < 2; mt++) {
                const int ar = wr * 32 + mt * 16 + g;
                a[mt][0] = __float_as_uint(Ab[ar * AST + acl]);
                a[mt][1] = __float_as_uint(Ab[(ar + 8) * AST + acl]);
                a[mt][2] = __float_as_uint(Ab[ar * AST + acl + 4]);
                a[mt][3] = __float_as_uint(Ab[(ar + 8) * AST + acl + 4]);
            }
            #pragma unroll
            for (int nt = 0; nt < 8; nt++) {
                uint32_t rb[2];
                const int bn = wc * 64 + nt * 8 + g;
                const int bk = ks * 8 + tg;
                rb[0] = __float_as_uint(Bb[bk * BST + bn]);
                rb[1] = __float_as_uint(Bb[(bk + 4) * BST + bn]);
                mma_tf32(C[0][nt], a[0], rb);
                mma_tf32(C[1][nt], a[1], rb);
            }
        }
        __syncthreads();
        if (it + 2 < NIT) ISSUE_STAGE(it + 2);
    }

    // epilogue: relu(+b1), dot w2; 4 row-partials per thread
    float p[2][2];
    p[0][0] = p[0][1] = p[1][0] = p[1][1] = 0.f;
    #pragma unroll
    for (int nt = 0; nt < 8; nt++) {
        int n0 = wc * 64 + nt * 8 + tg * 2;
        float bb0 = __ldg(&b1v[n0]), bb1 = __ldg(&b1v[n0 + 1]);
        float wv0 = __ldg(&w2[n0]),  wv1 = __ldg(&w2[n0 + 1]);
        #pragma unroll
        for (int mt = 0; mt < 2; mt++) {
            p[mt][0] = fmaf(fmaxf(C[mt][nt][0] + bb0, 0.f), wv0, p[mt][0]);
            p[mt][0] = fmaf(fmaxf(C[mt][nt][1] + bb1, 0.f), wv1, p[mt][0]);
            p[mt][1] = fmaf(fmaxf(C[mt][nt][2] + bb0, 0.f), wv0, p[mt][1]);
            p[mt][1] = fmaf(fmaxf(C[mt][nt][3] + bb1, 0.f), wv1, p[mt][1]);
        }
    }
    __syncthreads();
    float* red = &As[0][0];  // 64 rows x 16 slots = 4KB
    #pragma unroll
    for (int mt = 0; mt < 2; mt++) {
        int r0 = wr * 32 + mt * 16 + g;
        red[r0 * 16 + wc * 4 + tg]       = p[mt][0];
        red[(r0 + 8) * 16 + wc * 4 + tg] = p[mt][1];
    }
    __syncthreads();
    if (tid < BMg) {
        float s = 0.f;
        #pragma unroll
        for (int i = 0; i < 16; i++) s += red[tid * 16 + i];
        s += __ldg(&b2[0]);
        g_weights[m0 + tid] = 1.f / (1.f + expf(-s));
    }
    #undef ISSUE_STAGE
}

// ---------------- Kmain: fused distances/softmax/refined/att + final loss
__global__ __launch_bounds__(512)
void kmain(const float* __restrict__ feat,
           const float* __restrict__ anchors,
           const float* __restrict__ pos,
           const float* __restrict__ clw,
           float* __restrict__ out_refined,
           float* __restrict__ out_att,
           float* __restrict__ out_scalar) {
    __shared__ float sA[An * Dn];         // 20KB anch (computed inline)
    __shared__ float sW[(An + 1) * Dn];   // 22KB anchVW
    __shared__ float sn2[An];
    __shared__ float red[32];
    __shared__ int   s_last;
    const int tid = threadIdx.x;
    for (int i = tid; i < An * Dn; i += 512) sA[i] = anchors[i] + pos[i];
    for (int i = tid; i < (An + 1) * Dn; i += 512) sW[i] = g_anchVW[i];
    __syncthreads();

    const int wid = tid >> 5, l = tid & 31;

    // in-block anchor norms
    if (wid < An) {
        float s = 0.f;
        #pragma unroll
        for (int kk = 0; kk < 16; kk++) {
            float v = sA[wid * Dn + kk * 32 + l];
            s = fmaf(v, v, s);
        }
        #pragma unroll
        for (int o = 16; o; o >>= 1) s += __shfl_xor_sync(0xffffffffu, s, o);
        if (l == 0) sn2[wid] = s;
    }
    __syncthreads();

    float cp_acc = 0.f;

    #pragma unroll 1
    for (int it = 0; it < 4; it++) {
        const int r = blockIdx.x * 64 + it * 16 + wid;
        const float* f = feat + (size_t)r * Dn;

        float4 fv[4];
        #pragma unroll
        for (int j = 0; j < 4; j++) fv[j] = *(const float4*)&f[j * 128 + l * 4];

        float v11[11];
        {
            float s = 0.f;
            #pragma unroll
            for (int j = 0; j < 4; j++) {
                s = fmaf(fv[j].x, fv[j].x, s); s = fmaf(fv[j].y, fv[j].y, s);
                s = fmaf(fv[j].z, fv[j].z, s); s = fmaf(fv[j].w, fv[j].w, s);
            }
            v11[10] = s;
        }
        #pragma unroll
        for (int a = 0; a < An; a++) {
            float d = 0.f;
            #pragma unroll
            for (int j = 0; j < 4; j++) {
                float4 av = *(const float4*)&sA[a * Dn + j * 128 + l * 4];
                d = fmaf(fv[j].x, av.x, d); d = fmaf(fv[j].y, av.y, d);
                d = fmaf(fv[j].z, av.z, d); d = fmaf(fv[j].w, av.w, d);
            }
            v11[a] = d;
        }
        #pragma unroll
        for (int a = 0; a < 11; a++) {
            #pragma unroll
            for (int o = 16; o; o >>= 1) v11[a] += __shfl_xor_sync(0xffffffffu, v11[a], o);
        }

        const float fn2 = v11[10];
        const float inv_temp = rsqrtf(fn2);
        float att[An];
        float mx = -1e30f;
        #pragma unroll
        for (int a = 0; a < An; a++) {
            float d2 = fn2 - 2.f * v11[a] + sn2[a];
            float dist = sqrtf(fmaxf(d2, 0.f));
            float lg = -dist * inv_temp;
            att[a] = lg;
            mx = fmaxf(mx, lg);
        }
        float se = 0.f;
        #pragma unroll
        for (int a = 0; a < An; a++) { att[a] = __expf(att[a] - mx); se += att[a]; }
        const float inv_se = 1.f / se;
        #pragma unroll
        for (int a = 0; a < An; a++) att[a] *= inv_se;

        const float w = g_weights[r];

        float cp = 0.f;
        #pragma unroll
        for (int j = 0; j < 4; j++) {
            int base = j * 128 + l * 4;
            float4 cb = *(const float4*)&sW[An * Dn + base];
            float4 ac = make_float4(0.f, 0.f, 0.f, 0.f);
            #pragma unroll
            for (int a = 0; a < An; a++) {
                float4 av = *(const float4*)&sW[a * Dn + base];
                ac.x = fmaf(att[a], av.x, ac.x); ac.y = fmaf(att[a], av.y, ac.y);
                ac.z = fmaf(att[a], av.z, ac.z); ac.w = fmaf(att[a], av.w, ac.w);
            }
            float4 rr;
            rr.x = fmaf(w, ac.x, cb.x); rr.y = fmaf(w, ac.y, cb.y);
            rr.z = fmaf(w, ac.z, cb.z); rr.w = fmaf(w, ac.w, cb.w);
            *(float4*)&out_refined[(size_t)r * Dn + base] = rr;
            float dx = fv[j].x - rr.x; cp = fmaf(dx, dx, cp);
            dx = fv[j].y - rr.y; cp = fmaf(dx, dx, cp);
            dx = fv[j].z - rr.z; cp = fmaf(dx, dx, cp);
            dx = fv[j].w - rr.w; cp = fmaf(dx, dx, cp);
        }

        #pragma unroll
        for (int a = 0; a < An; a++)
            if (l == a) out_att[(size_t)r * An + a] = att[a];

        cp_acc += cp;
    }

    #pragma unroll
    for (int o = 16; o; o >>= 1) cp_acc += __shfl_xor_sync(0xffffffffu, cp_acc, o);
    if (l == 0) red[wid] = cp_acc;
    __syncthreads();
    if (tid == 0) {
        float t = 0.f;
        #pragma unroll
        for (int i = 0; i < 16; i++) t += red[i];
        g_partials[blockIdx.x] = t;
        __threadfence();
        int old = atomicAdd(&g_ticket, 1);
        s_last = (old == KMAIN_BLOCKS - 1) ? 1 : 0;
    }
    __syncthreads();

    // last block computes total_loss (deterministic fixed-order sums)
    if (s_last) {
        const int w = wid;
        float s = (tid < KMAIN_BLOCKS) ? g_partials[tid] : 0.f;
        #pragma unroll
        for (int o = 16; o; o >>= 1) s += __shfl_xor_sync(0xffffffffu, s, o);
        if (l == 0) red[w] = s;

        float pd = 0.f;
        #pragma unroll
        for (int pp = 0; pp < 3; pp++) {
            int p = w + pp * 16;
            if (p < 45) {  // warp-uniform
                int i = 0, q = p;
                while (q >= 9 - i) { q -= 9 - i; i++; }
                int j = i + 1 + q;
                float ss = 0.f;
                #pragma unroll
                for (int dd = 0; dd < 16; dd++) {
                    float df = anchors[i * Dn + dd * 32 + l] -
                               anchors[j * Dn + dd * 32 + l];
                    ss = fmaf(df, df, ss);
                }
                #pragma unroll
                for (int o = 16; o; o >>= 1) ss += __shfl_xor_sync(0xffffffffu, ss, o);
                pd += sqrtf(fmaxf(ss, 0.f));
            }
        }
        if (l == 0) red[16 + w] = pd;
        __syncthreads();
        if (tid == 0) {
            float c = 0.f, d = 0.f;
            #pragma unroll
            for (int i = 0; i < 16; i++) { c += red[i]; d += red[16 + i]; }
            float center = c * (1.f / (float)Bn);
            float div = -(d / 45.f);
            out_scalar[0] = clw[0] * center + 0.1f * div;
            g_ticket = 0;   // reset for next graph replay
        }
    }
}

// ---------------- launch (kmain at index 3 = the ncu capture slot) -------
extern "C" void kernel_launch(void* const* d_in, const int* in_sizes, int n_in,
                              void* d_out, int out_size) {
    const float* features = (const float*)d_in[0];
    const float* anchors  = (const float*)d_in[1];
    const float* pos      = (const float*)d_in[2];
    const float* qkv_w    = (const float*)d_in[3];
    const float* qkv_b    = (const float*)d_in[4];
    const float* proj_w   = (const float*)d_in[5];
    const float* proj_b   = (const float*)d_in[6];
    const float* w1       = (const float*)d_in[7];
    const float* b1       = (const float*)d_in[8];
    const float* w2       = (const float*)d_in[9];
    const float* b2       = (const float*)d_in[10];
    const float* clw      = (const float*)d_in[11];

    float* out         = (float*)d_out;
    float* out_refined = out;                        // B*D
    float* out_scalar  = out + (size_t)Bn * Dn;      // 1
    float* out_att     = out + (size_t)Bn * Dn + 1;  // B*A

    k1_part<<<dim3(2, KSPLIT), 256>>>(qkv_w, anchors, pos);             // 0
    k2_part<<<dim3(2, KSPLIT), 256>>>(proj_w, qkv_b);                   // 1
    kgemm_weights<<<Bn / BMg, 256>>>(features, w1, b1, w2, b2, proj_b); // 2
    kmain<<<KMAIN_BLOCKS, 512>>>(features, anchors, pos, clw,
                                 out_refined, out_att, out_scalar);     // 3 <- profiled
}

// round 9
// speedup vs baseline: 2.2424x; 1.4888x over previous
#include <cuda_runtime.h>
#include <math.h>
#include <stdint.h>

#define Bn 16384
#define Dn 512
#define An 10
#define KMAIN_BLOCKS 1024
#define KSPLIT 8          // k-chunks for k1/k2 partials
#define KCH (Dn / KSPLIT) // 64

// ---------------- scratch (no allocations allowed) ----------------
__device__ float g_anch[An * Dn];             // anchors + pos (written by k1_part)
__device__ float g_part[KSPLIT * (An + 1) * Dn];   // k1 partials
__device__ float g_part2[KSPLIT * (An + 1) * Dn];  // k2 partials
__device__ float g_anchVW[(An + 1) * Dn];     // (anch@Wv)@proj_w ; row10 = cbias
__device__ float g_weights[Bn];               // sigmoid gate per row
__device__ float g_partials[KMAIN_BLOCKS];    // center-loss per-block partials
__device__ int   g_ticket;                    // last-block ticket (reset each run)

// ---------------- K1 part: partial anchV over a k-chunk ------------------
// anch computed inline; block x==0 also persists it to g_anch.
__global__ void k1_part(const float* __restrict__ qkv_w,
                        const float* __restrict__ anchors,
                        const float* __restrict__ pos) {
    __shared__ float sa[An * KCH];
    const int tid = threadIdx.x;
    const int kc = blockIdx.y, k0 = kc * KCH;
    const int j = blockIdx.x * 256 + tid;
    for (int i = tid; i < An * KCH; i += 256) {
        int a = i / KCH, k = i % KCH;
        int gi = a * Dn + k0 + k;
        float v = anchors[gi] + pos[gi];
        sa[i] = v;
        if (blockIdx.x == 0) g_anch[gi] = v;
    }
    __syncthreads();
    float acc[An];
    #pragma unroll
    for (int a = 0; a < An; a++) acc[a] = 0.f;
    #pragma unroll 8
    for (int k = 0; k < KCH; k++) {
        float w = __ldg(&qkv_w[(size_t)(k0 + k) * (3 * Dn) + 2 * Dn + j]);
        #pragma unroll
        for (int a = 0; a < An; a++) acc[a] = fmaf(sa[a * KCH + k], w, acc[a]);
    }
    #pragma unroll
    for (int a = 0; a < An; a++)
        g_part[kc * ((An + 1) * Dn) + a * Dn + j] = acc[a];
}

// ---------------- K2 part: fuses k1-reduce into the smem staging ---------
__global__ void k2_part(const float* __restrict__ proj_w,
                        const float* __restrict__ qkv_b) {
    __shared__ float sa[(An + 1) * KCH];
    const int tid = threadIdx.x;
    const int kc = blockIdx.y, k0 = kc * KCH;
    const int d = blockIdx.x * 256 + tid;
    for (int i = tid; i < (An + 1) * KCH; i += 256) {
        int a = i / KCH, k = i % KCH;
        float v;
        if (a == An) {
            v = qkv_b[2 * Dn + k0 + k];
        } else {
            v = 0.f;
            #pragma unroll
            for (int c = 0; c < KSPLIT; c++)
                v += g_part[c * ((An + 1) * Dn) + a * Dn + k0 + k];
        }
        sa[i] = v;
    }
    __syncthreads();
    float acc[An + 1];
    #pragma unroll
    for (int a = 0; a <= An; a++) acc[a] = 0.f;
    #pragma unroll 8
    for (int k = 0; k < KCH; k++) {
        float w = __ldg(&proj_w[(size_t)(k0 + k) * Dn + d]);
        #pragma unroll
        for (int a = 0; a <= An; a++) acc[a] = fmaf(sa[a * KCH + k], w, acc[a]);
    }
    #pragma unroll
    for (int a = 0; a <= An; a++)
        g_part2[kc * ((An + 1) * Dn) + a * Dn + d] = acc[a];
}

// ---------------- Kgemm: weights + fused k2_reduce (unchanged from R8) ---
#define BMg 64
#define BKg 16
#define AST 20
#define BST 264

__device__ __forceinline__ void mma_tf32(float c[4], const uint32_t a[4],
                                         const uint32_t b[2]) {
    asm volatile(
        "mma.sync.aligned.m16n8k8.row.col.f32.tf32.tf32.f32 "
        "{%0,%1,%2,%3}, {%4,%5,%6,%7}, {%8,%9}, {%0,%1,%2,%3};"
        : "+f"(c[0]), "+f"(c[1]), "+f"(c[2]), "+f"(c[3])
        : "r"(a[0]), "r"(a[1]), "r"(a[2]), "r"(a[3]), "r"(b[0]), "r"(b[1]));
}

__device__ __forceinline__ void cp16(uint32_t dst, const float* src) {
    asm volatile("cp.async.ca.shared.global [%0], [%1], 16;\n"
                 :: "r"(dst), "l"(src));
}
__device__ __forceinline__ void cp_commit() {
    asm volatile("cp.async.commit_group;\n" ::: "memory");
}
template <int N>
__device__ __forceinline__ void cp_wait() {
    asm volatile("cp.async.wait_group %0;\n" :: "n"(N) : "memory");
}

__global__ __launch_bounds__(256)
void kgemm_weights(const float* __restrict__ f,
                   const float* __restrict__ w1,
                   const float* __restrict__ b1v,
                   const float* __restrict__ w2,
                   const float* __restrict__ b2,
                   const float* __restrict__ proj_b) {
    __shared__ float As[2][BMg * AST];   // 2 x 5.0KB
    __shared__ float Bs[2][BKg * BST];   // 2 x 16.5KB
    const int tid = threadIdx.x;
    const int wid = tid >> 5, l = tid & 31;
    const int wr = wid & 1;              // rows wr*32..+32
    const int wc = wid >> 1;             // cols wc*64..+64
    const int g = l >> 2, tg = l & 3;
    const int m0 = blockIdx.x * BMg;

    // fused k2_reduce: blocks 0..An finalize anchVW row blockIdx.x
    if (blockIdx.x <= An) {
        const int a = blockIdx.x;
        for (int d = tid; d < Dn; d += 256) {
            float s = 0.f;
            #pragma unroll
            for (int kc = 0; kc < KSPLIT; kc++)
                s += g_part2[kc * ((An + 1) * Dn) + a * Dn + d];
            if (a == An) s += proj_b[d];
            g_anchVW[a * Dn + d] = s;
        }
    }

    const uint32_t sA0 = (uint32_t)__cvta_generic_to_shared(&As[0][0]);
    const uint32_t sA1 = (uint32_t)__cvta_generic_to_shared(&As[1][0]);
    const uint32_t sB0 = (uint32_t)__cvta_generic_to_shared(&Bs[0][0]);
    const uint32_t sB1 = (uint32_t)__cvta_generic_to_shared(&Bs[1][0]);

    const int arow = tid >> 2, ac4 = tid & 3;  // A: 1 float4 per thread

    #define ISSUE_STAGE(s) do {                                              \
        int _buf = (s) & 1; int _k0 = (s) * BKg;                             \
        uint32_t _a = _buf ? sA1 : sA0, _b = _buf ? sB1 : sB0;               \
        cp16(_a + (arow * AST + ac4 * 4) * 4,                                \
             &f[(size_t)(m0 + arow) * Dn + _k0 + ac4 * 4]);                  \
        _Pragma("unroll")                                                    \
        for (int _p = 0; _p < 4; _p++) {                                     \
            int _idx = tid + _p * 256;                                       \
            int _kr = _idx >> 6, _n4 = _idx & 63;                            \
            cp16(_b + (_kr * BST + _n4 * 4) * 4,                             \
                 &w1[(size_t)(_k0 + _kr) * 256 + _n4 * 4]);                  \
        }                                                                    \
        cp_commit();                                                         \
    } while (0)

    float C[2][8][4];
    #pragma unroll
    for (int mt = 0; mt < 2; mt++)
        #pragma unroll
        for (int nt = 0; nt < 8; nt++)
            #pragma unroll
            for (int i = 0; i < 4; i++) C[mt][nt][i] = 0.f;

    ISSUE_STAGE(0);
    ISSUE_STAGE(1);

    const int NIT = Dn / BKg;  // 32
    for (int it = 0; it < NIT; it++) {
        cp_wait<1>();
        __syncthreads();
        const float* Ab = As[it & 1];
        const float* Bb = Bs[it & 1];
        #pragma unroll
        for (int ks = 0; ks < 2; ks++) {
            uint32_t a[2][4];
            const int acl = ks * 8 + tg;
            #pragma unroll
            for (int mt = 0; mt < 2; mt++) {
                const int ar = wr * 32 + mt * 16 + g;
                a[mt][0] = __float_as_uint(Ab[ar * AST + acl]);
                a[mt][1] = __float_as_uint(Ab[(ar + 8) * AST + acl]);
                a[mt][2] = __float_as_uint(Ab[ar * AST + acl + 4]);
                a[mt][3] = __float_as_uint(Ab[(ar + 8) * AST + acl + 4]);
            }
            #pragma unroll
            for (int nt = 0; nt < 8; nt++) {
                uint32_t rb[2];
                const int bn = wc * 64 + nt * 8 + g;
                const int bk = ks * 8 + tg;
                rb[0] = __float_as_uint(Bb[bk * BST + bn]);
                rb[1] = __float_as_uint(Bb[(bk + 4) * BST + bn]);
                mma_tf32(C[0][nt], a[0], rb);
                mma_tf32(C[1][nt], a[1], rb);
            }
        }
        __syncthreads();
        if (it + 2 < NIT) ISSUE_STAGE(it + 2);
    }

    float p[2][2];
    p[0][0] = p[0][1] = p[1][0] = p[1][1] = 0.f;
    #pragma unroll
    for (int nt = 0; nt < 8; nt++) {
        int n0 = wc * 64 + nt * 8 + tg * 2;
        float bb0 = __ldg(&b1v[n0]), bb1 = __ldg(&b1v[n0 + 1]);
        float wv0 = __ldg(&w2[n0]),  wv1 = __ldg(&w2[n0 + 1]);
        #pragma unroll
        for (int mt = 0; mt < 2; mt++) {
            p[mt][0] = fmaf(fmaxf(C[mt][nt][0] + bb0, 0.f), wv0, p[mt][0]);
            p[mt][0] = fmaf(fmaxf(C[mt][nt][1] + bb1, 0.f), wv1, p[mt][0]);
            p[mt][1] = fmaf(fmaxf(C[mt][nt][2] + bb0, 0.f), wv0, p[mt][1]);
            p[mt][1] = fmaf(fmaxf(C[mt][nt][3] + bb1, 0.f), wv1, p[mt][1]);
        }
    }
    __syncthreads();
    float* red = &As[0][0];  // 64 rows x 16 slots = 4KB
    #pragma unroll
    for (int mt = 0; mt < 2; mt++) {
        int r0 = wr * 32 + mt * 16 + g;
        red[r0 * 16 + wc * 4 + tg]       = p[mt][0];
        red[(r0 + 8) * 16 + wc * 4 + tg] = p[mt][1];
    }
    __syncthreads();
    if (tid < BMg) {
        float s = 0.f;
        #pragma unroll
        for (int i = 0; i < 16; i++) s += red[tid * 16 + i];
        s += __ldg(&b2[0]);
        g_weights[m0 + tid] = 1.f / (1.f + expf(-s));
    }
    #undef ISSUE_STAGE
}

// ---------------- Kmain v2: 1024 blocks x 16 rows, 8 warps ---------------
// anchors via __ldg (L1-resident), features via __ldcg (L2-only, no L1
// pollution), anchVW in smem (22.5KB). Final loss fused via ticket.
__global__ __launch_bounds__(256)
void kmain(const float* __restrict__ feat,
           const float* __restrict__ anchors,
           const float* __restrict__ clw,
           float* __restrict__ out_refined,
           float* __restrict__ out_att,
           float* __restrict__ out_scalar) {
    __shared__ float sW[(An + 1) * Dn];   // 22.5KB anchVW
    __shared__ float sn2[An];
    __shared__ float sAtt[8 * An];
    __shared__ float red[32];
    __shared__ int   s_last;
    const int tid = threadIdx.x;
    const int wid = tid >> 5, l = tid & 31;

    for (int i = tid; i < (An + 1) * Dn; i += 256) sW[i] = g_anchVW[i];

    // anchor norms (8 warps cover 10 anchors in 2 rounds)
    for (int a = wid; a < An; a += 8) {
        float s = 0.f;
        #pragma unroll
        for (int kk = 0; kk < 16; kk++) {
            float v = __ldg(&g_anch[a * Dn + kk * 32 + l]);
            s = fmaf(v, v, s);
        }
        #pragma unroll
        for (int o = 16; o; o >>= 1) s += __shfl_xor_sync(0xffffffffu, s, o);
        if (l == 0) sn2[a] = s;
    }
    __syncthreads();

    float cp_acc = 0.f;

    #pragma unroll 1
    for (int it = 0; it < 2; it++) {
        const int r = blockIdx.x * 16 + it * 8 + wid;
        const float* f = feat + (size_t)r * Dn;

        float4 fv[4];
        #pragma unroll
        for (int j = 0; j < 4; j++)
            fv[j] = __ldcg((const float4*)&f[j * 128 + l * 4]);

        float v11[11];
        {
            float s = 0.f;
            #pragma unroll
            for (int j = 0; j < 4; j++) {
                s = fmaf(fv[j].x, fv[j].x, s); s = fmaf(fv[j].y, fv[j].y, s);
                s = fmaf(fv[j].z, fv[j].z, s); s = fmaf(fv[j].w, fv[j].w, s);
            }
            v11[10] = s;
        }
        #pragma unroll
        for (int a = 0; a < An; a++) {
            float d = 0.f;
            #pragma unroll
            for (int j = 0; j < 4; j++) {
                float4 av = __ldg((const float4*)&g_anch[a * Dn + j * 128 + l * 4]);
                d = fmaf(fv[j].x, av.x, d); d = fmaf(fv[j].y, av.y, d);
                d = fmaf(fv[j].z, av.z, d); d = fmaf(fv[j].w, av.w, d);
            }
            v11[a] = d;
        }
        #pragma unroll
        for (int a = 0; a < 11; a++) {
            #pragma unroll
            for (int o = 16; o; o >>= 1) v11[a] += __shfl_xor_sync(0xffffffffu, v11[a], o);
        }

        const float fn2 = v11[10];
        const float inv_temp = rsqrtf(fn2);
        float att[An];
        float mx = -1e30f;
        #pragma unroll
        for (int a = 0; a < An; a++) {
            float d2 = fn2 - 2.f * v11[a] + sn2[a];
            float dist = sqrtf(fmaxf(d2, 0.f));
            float lg = -dist * inv_temp;
            att[a] = lg;
            mx = fmaxf(mx, lg);
        }
        float se = 0.f;
        #pragma unroll
        for (int a = 0; a < An; a++) { att[a] = __expf(att[a] - mx); se += att[a]; }
        const float inv_se = 1.f / se;
        #pragma unroll
        for (int a = 0; a < An; a++) att[a] *= inv_se;

        const float w = g_weights[r];

        float cp = 0.f;
        #pragma unroll
        for (int j = 0; j < 4; j++) {
            int base = j * 128 + l * 4;
            float4 cb = *(const float4*)&sW[An * Dn + base];
            float4 ac = make_float4(0.f, 0.f, 0.f, 0.f);
            #pragma unroll
            for (int a = 0; a < An; a++) {
                float4 av = *(const float4*)&sW[a * Dn + base];
                ac.x = fmaf(att[a], av.x, ac.x); ac.y = fmaf(att[a], av.y, ac.y);
                ac.z = fmaf(att[a], av.z, ac.z); ac.w = fmaf(att[a], av.w, ac.w);
            }
            float4 rr;
            rr.x = fmaf(w, ac.x, cb.x); rr.y = fmaf(w, ac.y, cb.y);
            rr.z = fmaf(w, ac.z, cb.z); rr.w = fmaf(w, ac.w, cb.w);
            *(float4*)&out_refined[(size_t)r * Dn + base] = rr;
            float dx = fv[j].x - rr.x; cp = fmaf(dx, dx, cp);
            dx = fv[j].y - rr.y; cp = fmaf(dx, dx, cp);
            dx = fv[j].z - rr.z; cp = fmaf(dx, dx, cp);
            dx = fv[j].w - rr.w; cp = fmaf(dx, dx, cp);
        }

        // coalesced att store: lane a of each warp deposits att[a]
        if (l < An) sAtt[wid * An + l] = att[l];
        __syncthreads();
        if (tid < 8 * An)
            out_att[(size_t)(blockIdx.x * 16 + it * 8) * An + tid] = sAtt[tid];
        __syncthreads();

        cp_acc += cp;
    }

    #pragma unroll
    for (int o = 16; o; o >>= 1) cp_acc += __shfl_xor_sync(0xffffffffu, cp_acc, o);
    if (l == 0) red[wid] = cp_acc;
    __syncthreads();
    if (tid == 0) {
        float t = 0.f;
        #pragma unroll
        for (int i = 0; i < 8; i++) t += red[i];
        g_partials[blockIdx.x] = t;
        __threadfence();
        int old = atomicAdd(&g_ticket, 1);
        s_last = (old == KMAIN_BLOCKS - 1) ? 1 : 0;
    }
    __syncthreads();

    // last block computes total_loss (deterministic fixed-order sums)
    if (s_last) {
        float s = g_partials[tid] + g_partials[tid + 256] +
                  g_partials[tid + 512] + g_partials[tid + 768];
        #pragma unroll
        for (int o = 16; o; o >>= 1) s += __shfl_xor_sync(0xffffffffu, s, o);
        if (l == 0) red[wid] = s;

        float pd = 0.f;
        #pragma unroll
        for (int pp = 0; pp < 6; pp++) {
            int p = wid + pp * 8;
            if (p < 45) {  // warp-uniform
                int i = 0, q = p;
                while (q >= 9 - i) { q -= 9 - i; i++; }
                int j = i + 1 + q;
                float ss = 0.f;
                #pragma unroll
                for (int dd = 0; dd < 16; dd++) {
                    float df = anchors[i * Dn + dd * 32 + l] -
                               anchors[j * Dn + dd * 32 + l];
                    ss = fmaf(df, df, ss);
                }
                #pragma unroll
                for (int o = 16; o; o >>= 1) ss += __shfl_xor_sync(0xffffffffu, ss, o);
                pd += sqrtf(fmaxf(ss, 0.f));
            }
        }
        if (l == 0) red[16 + wid] = pd;
        __syncthreads();
        if (tid == 0) {
            float c = 0.f, d = 0.f;
            #pragma unroll
            for (int i = 0; i < 8; i++) { c += red[i]; d += red[16 + i]; }
            float center = c * (1.f / (float)Bn);
            float div = -(d / 45.f);
            out_scalar[0] = clw[0] * center + 0.1f * div;
            g_ticket = 0;   // reset for next graph replay
        }
    }
}

// ---------------- launch (kmain at index 3 = the ncu capture slot) -------
extern "C" void kernel_launch(void* const* d_in, const int* in_sizes, int n_in,
                              void* d_out, int out_size) {
    const float* features = (const float*)d_in[0];
    const float* anchors  = (const float*)d_in[1];
    const float* pos      = (const float*)d_in[2];
    const float* qkv_w    = (const float*)d_in[3];
    const float* qkv_b    = (const float*)d_in[4];
    const float* proj_w   = (const float*)d_in[5];
    const float* proj_b   = (const float*)d_in[6];
    const float* w1       = (const float*)d_in[7];
    const float* b1       = (const float*)d_in[8];
    const float* w2       = (const float*)d_in[9];
    const float* b2       = (const float*)d_in[10];
    const float* clw      = (const float*)d_in[11];

    float* out         = (float*)d_out;
    float* out_refined = out;                        // B*D
    float* out_scalar  = out + (size_t)Bn * Dn;      // 1
    float* out_att     = out + (size_t)Bn * Dn + 1;  // B*A

    k1_part<<<dim3(2, KSPLIT), 256>>>(qkv_w, anchors, pos);             // 0
    k2_part<<<dim3(2, KSPLIT), 256>>>(proj_w, qkv_b);                   // 1
    kgemm_weights<<<Bn / BMg, 256>>>(features, w1, b1, w2, b2, proj_b); // 2
    kmain<<<KMAIN_BLOCKS, 256>>>(features, anchors, clw,
                                 out_refined, out_att, out_scalar);     // 3 <- profiled
}